// round 1
// baseline (speedup 1.0000x reference)
#include <cuda_runtime.h>
#include <math.h>

#define B 8
#define D 512
#define L 2048

#define BLD (8u*2048u*512u)          // 8388608
__device__ float g_kqv[3ull * BLD];  // [which(K,Q,V)][b][l][d]

#define BM 128
#define BN 128
#define BK 8
#define PAD 4
#define SMW (BM + PAD)

__device__ __forceinline__ float elu_f(float x) {
    return x > 0.0f ? x : expm1f(x);
}

// ---------------------------------------------------------------------------
// Projection: out[b,l,o] = ELU( sum_i W[o,i] * H[b,i,l] + bias[o] )
// A[l,i] = H[b, i, l]  (l contiguous)  ;  B[o,i] = W[o*D + i] (i contiguous)
// grid: (L/BM=16, D/BN=4, B*3=24), 256 threads
// ---------------------------------------------------------------------------
__global__ __launch_bounds__(256) void proj_kernel(
    const float* __restrict__ H,
    const float* __restrict__ Wk, const float* __restrict__ bk,
    const float* __restrict__ Wq, const float* __restrict__ bq,
    const float* __restrict__ Wv, const float* __restrict__ bv)
{
    int bz = blockIdx.z;
    int b = bz / 3, which = bz % 3;
    const float* W    = (which == 0) ? Wk : (which == 1) ? Wq : Wv;
    const float* bias = (which == 0) ? bk : (which == 1) ? bq : bv;
    float* dst = g_kqv + (size_t)which * BLD + (size_t)b * L * D;

    __shared__ float As[BK][SMW];  // As[i][l]
    __shared__ float Bs[BK][SMW];  // Bs[i][o]

    const int m0 = blockIdx.x * BM;   // l
    const int n0 = blockIdx.y * BN;   // o
    const float* Hb = H + (size_t)b * D * L;

    const int tid = threadIdx.x;
    const int tx = tid % 16;
    const int ty = tid / 16;

    float acc[8][8];
    #pragma unroll
    for (int i = 0; i < 8; i++)
        #pragma unroll
        for (int j = 0; j < 8; j++) acc[i][j] = 0.0f;

    for (int k0 = 0; k0 < D; k0 += BK) {
        // A tile: column (k0+i) of H is contiguous in l
        {
            int i = tid >> 5;            // 0..7
            int l = (tid & 31) << 2;     // 0..124
            float4 v = *(const float4*)(Hb + (size_t)(k0 + i) * L + m0 + l);
            *(float4*)(&As[i][l]) = v;
        }
        // B tile: W row (n0+o), 8 contiguous k; transpose into Bs
        {
            int o = tid >> 1;            // 0..127
            int i = (tid & 1) << 2;      // 0 or 4
            float4 v = *(const float4*)(W + (size_t)(n0 + o) * D + k0 + i);
            Bs[i + 0][o] = v.x; Bs[i + 1][o] = v.y;
            Bs[i + 2][o] = v.z; Bs[i + 3][o] = v.w;
        }
        __syncthreads();
        #pragma unroll
        for (int k = 0; k < BK; k++) {
            float a[8], bb[8];
            *(float4*)&a[0]  = *(float4*)&As[k][ty * 4];
            *(float4*)&a[4]  = *(float4*)&As[k][64 + ty * 4];
            *(float4*)&bb[0] = *(float4*)&Bs[k][tx * 4];
            *(float4*)&bb[4] = *(float4*)&Bs[k][64 + tx * 4];
            #pragma unroll
            for (int i = 0; i < 8; i++)
                #pragma unroll
                for (int j = 0; j < 8; j++)
                    acc[i][j] = fmaf(a[i], bb[j], acc[i][j]);
        }
        __syncthreads();
    }

    #pragma unroll
    for (int i = 0; i < 8; i++) {
        int l = m0 + (i / 4) * 64 + ty * 4 + (i % 4);
        int o0 = n0 + tx * 4;
        int o1 = n0 + 64 + tx * 4;
        float4 v0, v1;
        v0.x = elu_f(acc[i][0] + bias[o0 + 0]);
        v0.y = elu_f(acc[i][1] + bias[o0 + 1]);
        v0.z = elu_f(acc[i][2] + bias[o0 + 2]);
        v0.w = elu_f(acc[i][3] + bias[o0 + 3]);
        v1.x = elu_f(acc[i][4] + bias[o1 + 0]);
        v1.y = elu_f(acc[i][5] + bias[o1 + 1]);
        v1.z = elu_f(acc[i][6] + bias[o1 + 2]);
        v1.w = elu_f(acc[i][7] + bias[o1 + 3]);
        *(float4*)(dst + (size_t)l * D + o0) = v0;
        *(float4*)(dst + (size_t)l * D + o1) = v1;
    }
}

// ---------------------------------------------------------------------------
// E[b,q,k] = scale * sum_d Q[b,q,d] * K[b,k,d]
// grid: (16, 16, 8), 256 threads
// ---------------------------------------------------------------------------
__global__ __launch_bounds__(256) void e_kernel(float* __restrict__ E)
{
    const int b = blockIdx.z;
    const float* Qb = g_kqv + 1ull * BLD + (size_t)b * L * D;
    const float* Kb = g_kqv + 0ull * BLD + (size_t)b * L * D;
    float* dst = E + (size_t)b * L * L;

    __shared__ float As[BK][SMW];  // As[d][q]
    __shared__ float Bs[BK][SMW];  // Bs[d][k]

    const int m0 = blockIdx.x * BM;   // q
    const int n0 = blockIdx.y * BN;   // k
    const int tid = threadIdx.x;
    const int tx = tid % 16;
    const int ty = tid / 16;
    const float scale = 0.04419417382415922f;  // 1/sqrt(512)

    float acc[8][8];
    #pragma unroll
    for (int i = 0; i < 8; i++)
        #pragma unroll
        for (int j = 0; j < 8; j++) acc[i][j] = 0.0f;

    for (int k0 = 0; k0 < D; k0 += BK) {
        {
            int q = tid >> 1;
            int d = (tid & 1) << 2;
            float4 v = *(const float4*)(Qb + (size_t)(m0 + q) * D + k0 + d);
            As[d + 0][q] = v.x; As[d + 1][q] = v.y;
            As[d + 2][q] = v.z; As[d + 3][q] = v.w;
        }
        {
            int kk = tid >> 1;
            int d = (tid & 1) << 2;
            float4 v = *(const float4*)(Kb + (size_t)(n0 + kk) * D + k0 + d);
            Bs[d + 0][kk] = v.x; Bs[d + 1][kk] = v.y;
            Bs[d + 2][kk] = v.z; Bs[d + 3][kk] = v.w;
        }
        __syncthreads();
        #pragma unroll
        for (int k = 0; k < BK; k++) {
            float a[8], bb[8];
            *(float4*)&a[0]  = *(float4*)&As[k][ty * 4];
            *(float4*)&a[4]  = *(float4*)&As[k][64 + ty * 4];
            *(float4*)&bb[0] = *(float4*)&Bs[k][tx * 4];
            *(float4*)&bb[4] = *(float4*)&Bs[k][64 + tx * 4];
            #pragma unroll
            for (int i = 0; i < 8; i++)
                #pragma unroll
                for (int j = 0; j < 8; j++)
                    acc[i][j] = fmaf(a[i], bb[j], acc[i][j]);
        }
        __syncthreads();
    }

    #pragma unroll
    for (int i = 0; i < 8; i++) {
        int q = m0 + (i / 4) * 64 + ty * 4 + (i % 4);
        float4 v0 = make_float4(acc[i][0] * scale, acc[i][1] * scale,
                                acc[i][2] * scale, acc[i][3] * scale);
        float4 v1 = make_float4(acc[i][4] * scale, acc[i][5] * scale,
                                acc[i][6] * scale, acc[i][7] * scale);
        *(float4*)(dst + (size_t)q * L + n0 + tx * 4) = v0;
        *(float4*)(dst + (size_t)q * L + n0 + 64 + tx * 4) = v1;
    }
}

// ---------------------------------------------------------------------------
// Row softmax over last dim (L=2048), in place. grid = B*L rows, 256 threads.
// ---------------------------------------------------------------------------
__global__ __launch_bounds__(256) void softmax_kernel(float* __restrict__ A)
{
    __shared__ float red[256];
    float* row = A + (size_t)blockIdx.x * L;
    const int tid = threadIdx.x;

    float v[8];
    float m = -INFINITY;
    #pragma unroll
    for (int j = 0; j < 8; j++) {
        v[j] = row[tid + j * 256];
        m = fmaxf(m, v[j]);
    }
    red[tid] = m;
    __syncthreads();
    #pragma unroll
    for (int s = 128; s > 0; s >>= 1) {
        if (tid < s) red[tid] = fmaxf(red[tid], red[tid + s]);
        __syncthreads();
    }
    m = red[0];
    __syncthreads();

    float sum = 0.0f;
    #pragma unroll
    for (int j = 0; j < 8; j++) {
        v[j] = expf(v[j] - m);
        sum += v[j];
    }
    red[tid] = sum;
    __syncthreads();
    #pragma unroll
    for (int s = 128; s > 0; s >>= 1) {
        if (tid < s) red[tid] += red[tid + s];
        __syncthreads();
    }
    float inv = 1.0f / red[0];
    #pragma unroll
    for (int j = 0; j < 8; j++) row[tid + j * 256] = v[j] * inv;
}

// ---------------------------------------------------------------------------
// C[b,q,d] = sum_k A[b,q,k] * V[b,k,d]
// grid: (16, 4, 8), 256 threads
// ---------------------------------------------------------------------------
__global__ __launch_bounds__(256) void c_kernel(
    const float* __restrict__ A, float* __restrict__ C)
{
    const int b = blockIdx.z;
    const float* Ab = A + (size_t)b * L * L;
    const float* Vb = g_kqv + 2ull * BLD + (size_t)b * L * D;
    float* dst = C + (size_t)b * L * D;

    __shared__ float As[BK][SMW];  // As[k][q]
    __shared__ float Bs[BK][SMW];  // Bs[k][d]

    const int m0 = blockIdx.x * BM;   // q
    const int n0 = blockIdx.y * BN;   // d
    const int tid = threadIdx.x;
    const int tx = tid % 16;
    const int ty = tid / 16;

    float acc[8][8];
    #pragma unroll
    for (int i = 0; i < 8; i++)
        #pragma unroll
        for (int j = 0; j < 8; j++) acc[i][j] = 0.0f;

    for (int k0 = 0; k0 < L; k0 += BK) {
        {
            int q = tid >> 1;
            int kk = (tid & 1) << 2;
            float4 v = *(const float4*)(Ab + (size_t)(m0 + q) * L + k0 + kk);
            As[kk + 0][q] = v.x; As[kk + 1][q] = v.y;
            As[kk + 2][q] = v.z; As[kk + 3][q] = v.w;
        }
        {
            int kr = tid >> 5;             // 0..7
            int d = (tid & 31) << 2;       // 0..124
            float4 v = *(const float4*)(Vb + (size_t)(k0 + kr) * D + n0 + d);
            *(float4*)(&Bs[kr][d]) = v;
        }
        __syncthreads();
        #pragma unroll
        for (int k = 0; k < BK; k++) {
            float a[8], bb[8];
            *(float4*)&a[0]  = *(float4*)&As[k][ty * 4];
            *(float4*)&a[4]  = *(float4*)&As[k][64 + ty * 4];
            *(float4*)&bb[0] = *(float4*)&Bs[k][tx * 4];
            *(float4*)&bb[4] = *(float4*)&Bs[k][64 + tx * 4];
            #pragma unroll
            for (int i = 0; i < 8; i++)
                #pragma unroll
                for (int j = 0; j < 8; j++)
                    acc[i][j] = fmaf(a[i], bb[j], acc[i][j]);
        }
        __syncthreads();
    }

    #pragma unroll
    for (int i = 0; i < 8; i++) {
        int q = m0 + (i / 4) * 64 + ty * 4 + (i % 4);
        float4 v0 = make_float4(acc[i][0], acc[i][1], acc[i][2], acc[i][3]);
        float4 v1 = make_float4(acc[i][4], acc[i][5], acc[i][6], acc[i][7]);
        *(float4*)(dst + (size_t)q * D + n0 + tx * 4) = v0;
        *(float4*)(dst + (size_t)q * D + n0 + 64 + tx * 4) = v1;
    }
}

// ---------------------------------------------------------------------------
extern "C" void kernel_launch(void* const* d_in, const int* in_sizes, int n_in,
                              void* d_out, int out_size)
{
    const float* H  = (const float*)d_in[0];
    const float* Wk = (const float*)d_in[1];
    const float* bk = (const float*)d_in[2];
    const float* Wq = (const float*)d_in[3];
    const float* bq = (const float*)d_in[4];
    const float* Wv = (const float*)d_in[5];
    const float* bv = (const float*)d_in[6];

    float* C_out = (float*)d_out;                    // [B, L, D]
    float* A_out = C_out + (size_t)B * L * D;        // [B, L, L]

    {
        dim3 grid(L / BM, D / BN, B * 3);
        proj_kernel<<<grid, 256>>>(H, Wk, bk, Wq, bq, Wv, bv);
    }
    {
        dim3 grid(L / BM, L / BN, B);
        e_kernel<<<grid, 256>>>(A_out);
    }
    {
        softmax_kernel<<<B * L, 256>>>(A_out);
    }
    {
        dim3 grid(L / BM, D / BN, B);
        c_kernel<<<grid, 256>>>(A_out, C_out);
    }
}

// round 3
// speedup vs baseline: 1.5046x; 1.5046x over previous
#include <cuda_runtime.h>
#include <cuda_bf16.h>
#include <math.h>
#include <stdint.h>

#define B 8
#define D 512
#define L 2048

#define BLD (8u*2048u*512u)            // 8388608
#define BLL (8ull*2048ull*2048ull)     // 33554432

// bf16 hi/lo split operands
__device__ __align__(128) __nv_bfloat16 gQh[BLD], gQl[BLD];
__device__ __align__(128) __nv_bfloat16 gKh[BLD], gKl[BLD];
__device__ __align__(128) __nv_bfloat16 gVth[BLD], gVtl[BLD];   // V^T: [b][d][l]
__device__ __align__(128) __nv_bfloat16 gAh[BLL], gAl[BLL];

// ---------------------------------------------------------------------------
__device__ __forceinline__ uint32_t smem_u32(const void* p) {
    uint32_t a;
    asm("{ .reg .u64 t; cvta.to.shared.u64 t, %1; cvt.u32.u64 %0, t; }"
        : "=r"(a) : "l"(p));
    return a;
}

__device__ __forceinline__ void ldsm_x4(uint32_t* r, uint32_t addr) {
    asm volatile("ldmatrix.sync.aligned.m8n8.x4.shared.b16 {%0,%1,%2,%3}, [%4];"
        : "=r"(r[0]), "=r"(r[1]), "=r"(r[2]), "=r"(r[3]) : "r"(addr));
}

__device__ __forceinline__ void mma_bf16(float* c, const uint32_t* a, const uint32_t* b) {
    asm volatile(
        "mma.sync.aligned.m16n8k16.row.col.f32.bf16.bf16.f32 "
        "{%0,%1,%2,%3}, {%4,%5,%6,%7}, {%8,%9}, {%0,%1,%2,%3};"
        : "+f"(c[0]), "+f"(c[1]), "+f"(c[2]), "+f"(c[3])
        : "r"(a[0]), "r"(a[1]), "r"(a[2]), "r"(a[3]), "r"(b[0]), "r"(b[1]));
}

__device__ __forceinline__ void cp16(uint32_t saddr, const void* gaddr) {
    asm volatile("cp.async.cg.shared.global [%0], [%1], 16;"
        :: "r"(saddr), "l"(gaddr) : "memory");
}
#define CP_COMMIT() asm volatile("cp.async.commit_group;" ::: "memory")
#define CP_WAIT1()  asm volatile("cp.async.wait_group 1;" ::: "memory")
#define CP_WAIT0()  asm volatile("cp.async.wait_group 0;" ::: "memory")

// ---------------------------------------------------------------------------
// 3-way split GEMM: Cout[m,n] = scale * sum_k (Ah+Al)[m,k]*(Bh+Bl)[n,k]
// CTA tile 128x128, K-chunk 32. 8 warps: warp = (wm 0..3)x(wn 0..1), 32x64 each.
// smem: 2 stages x 4 tiles (Ah,Al,Bh,Bl) x 128 rows x 80B (32 bf16 + pad).
// ---------------------------------------------------------------------------
#define ROWB  80
#define TILEB (128 * ROWB)          // 10240
#define STAGEB (4 * TILEB)          // 40960
#define MM3_SMEM (2 * STAGEB)       // 81920

__global__ __launch_bounds__(256, 1) void mm3_kernel(
    const __nv_bfloat16* __restrict__ Ah, const __nv_bfloat16* __restrict__ Al,
    size_t sA, int ldA,
    const __nv_bfloat16* __restrict__ Bh, const __nv_bfloat16* __restrict__ Bl,
    size_t sB, int ldB,
    float* __restrict__ Cout, size_t sC, int ldC,
    int nchunks, float scale)
{
    extern __shared__ char smem[];
    const uint32_t sbase = smem_u32(smem);
    const int tid = threadIdx.x, wid = tid >> 5, lane = tid & 31;
    const int wm = wid & 3, wn = wid >> 2;
    const int m0 = blockIdx.x * 128, n0 = blockIdx.y * 128, bz = blockIdx.z;

    const __nv_bfloat16* srcA_h = Ah + (size_t)bz * sA + (size_t)m0 * ldA;
    const __nv_bfloat16* srcA_l = Al + (size_t)bz * sA + (size_t)m0 * ldA;
    const __nv_bfloat16* srcB_h = Bh + (size_t)bz * sB + (size_t)n0 * ldB;
    const __nv_bfloat16* srcB_l = Bl + (size_t)bz * sB + (size_t)n0 * ldB;
    Cout += (size_t)bz * sC;

    // global->smem copy mapping: 512 (row,seg) pairs, each 16B; 2 per thread
    const int r0i = (tid * 2) >> 2,      s0i = (tid * 2) & 3;
    const int r1i = (tid * 2 + 1) >> 2,  s1i = (tid * 2 + 1) & 3;

#define ISSUE_CHUNK(ch) do { \
        const int _k0 = (ch) * 32; \
        const uint32_t _sb = sbase + ((ch) & 1) * STAGEB; \
        cp16(_sb + 0*TILEB + r0i*ROWB + s0i*16, srcA_h + (size_t)r0i*ldA + _k0 + s0i*8); \
        cp16(_sb + 0*TILEB + r1i*ROWB + s1i*16, srcA_h + (size_t)r1i*ldA + _k0 + s1i*8); \
        cp16(_sb + 1*TILEB + r0i*ROWB + s0i*16, srcA_l + (size_t)r0i*ldA + _k0 + s0i*8); \
        cp16(_sb + 1*TILEB + r1i*ROWB + s1i*16, srcA_l + (size_t)r1i*ldA + _k0 + s1i*8); \
        cp16(_sb + 2*TILEB + r0i*ROWB + s0i*16, srcB_h + (size_t)r0i*ldB + _k0 + s0i*8); \
        cp16(_sb + 2*TILEB + r1i*ROWB + s1i*16, srcB_h + (size_t)r1i*ldB + _k0 + s1i*8); \
        cp16(_sb + 3*TILEB + r0i*ROWB + s0i*16, srcB_l + (size_t)r0i*ldB + _k0 + s0i*8); \
        cp16(_sb + 3*TILEB + r1i*ROWB + s1i*16, srcB_l + (size_t)r1i*ldB + _k0 + s1i*8); \
        CP_COMMIT(); \
    } while (0)

    float acc[2][8][4];
    #pragma unroll
    for (int i = 0; i < 2; i++)
        #pragma unroll
        for (int j = 0; j < 8; j++)
            #pragma unroll
            for (int t = 0; t < 4; t++) acc[i][j][t] = 0.0f;

    // ldmatrix lane offsets (bytes within a tile)
    const int rowA_l = lane & 15;              // + kseg from lane>>4
    const uint32_t offA_l = (uint32_t)rowA_l * ROWB + (lane >> 4) * 16;
    const int rowB_l = (lane & 7) + ((lane & 16) ? 8 : 0);
    const uint32_t offB_l = (uint32_t)rowB_l * ROWB + ((lane & 8) ? 16 : 0);

    ISSUE_CHUNK(0);

    for (int ch = 0; ch < nchunks; ch++) {
        if (ch + 1 < nchunks) { ISSUE_CHUNK(ch + 1); CP_WAIT1(); }
        else                  { CP_WAIT0(); }
        __syncthreads();

        const uint32_t sb = sbase + (ch & 1) * STAGEB;
        #pragma unroll
        for (int ks = 0; ks < 2; ks++) {
            const uint32_t kb = ks * 32;   // 16 bf16 = 32 bytes
            uint32_t ah[2][4], al[2][4], bh[4][4], bl[4][4];
            #pragma unroll
            for (int i = 0; i < 2; i++) {
                uint32_t base = sb + (uint32_t)(wm * 32 + i * 16) * ROWB + kb;
                ldsm_x4(ah[i], base + 0*TILEB + offA_l);
                ldsm_x4(al[i], base + 1*TILEB + offA_l);
            }
            #pragma unroll
            for (int j2 = 0; j2 < 4; j2++) {
                uint32_t base = sb + (uint32_t)(wn * 64 + j2 * 16) * ROWB + kb;
                ldsm_x4(bh[j2], base + 2*TILEB + offB_l);
                ldsm_x4(bl[j2], base + 3*TILEB + offB_l);
            }
            #pragma unroll
            for (int i = 0; i < 2; i++)
                #pragma unroll
                for (int j = 0; j < 8; j++) {
                    const uint32_t* bhp = &bh[j >> 1][(j & 1) * 2];
                    const uint32_t* blp = &bl[j >> 1][(j & 1) * 2];
                    mma_bf16(acc[i][j], ah[i], bhp);
                    mma_bf16(acc[i][j], ah[i], blp);
                    mma_bf16(acc[i][j], al[i], bhp);
                }
        }
        __syncthreads();
    }
#undef ISSUE_CHUNK

    // epilogue
    const int g = lane >> 2, tg = lane & 3;
    #pragma unroll
    for (int i = 0; i < 2; i++) {
        const int r0 = m0 + wm * 32 + i * 16 + g;
        #pragma unroll
        for (int j = 0; j < 8; j++) {
            const int c = n0 + wn * 64 + j * 8 + tg * 2;
            float2 v0 = make_float2(acc[i][j][0] * scale, acc[i][j][1] * scale);
            float2 v1 = make_float2(acc[i][j][2] * scale, acc[i][j][3] * scale);
            *(float2*)(Cout + (size_t)r0 * ldC + c) = v0;
            *(float2*)(Cout + (size_t)(r0 + 8) * ldC + c) = v1;
        }
    }
}

// ---------------------------------------------------------------------------
// Projection (SIMT fp32 core) with split bf16 epilogue.
// K,Q -> [b][l][d] hi/lo ; V -> transposed [b][d][l] hi/lo
// ---------------------------------------------------------------------------
#define BM 128
#define BN 128
#define BK 8
#define PAD 4
#define SMW (BM + PAD)

__device__ __forceinline__ float elu_f(float x) {
    return x > 0.0f ? x : expm1f(x);
}

__device__ __forceinline__ void split4(const float* f, __nv_bfloat16* hi, __nv_bfloat16* lo) {
    __nv_bfloat16 h[4], l[4];
    #pragma unroll
    for (int i = 0; i < 4; i++) {
        h[i] = __float2bfloat16(f[i]);
        l[i] = __float2bfloat16(f[i] - __bfloat162float(h[i]));
    }
    *(uint2*)hi = *(const uint2*)h;
    *(uint2*)lo = *(const uint2*)l;
}

__global__ __launch_bounds__(256) void proj_kernel(
    const float* __restrict__ H,
    const float* __restrict__ Wk, const float* __restrict__ bk,
    const float* __restrict__ Wq, const float* __restrict__ bq,
    const float* __restrict__ Wv, const float* __restrict__ bv)
{
    int bz = blockIdx.z;
    int b = bz / 3, which = bz % 3;
    const float* W    = (which == 0) ? Wk : (which == 1) ? Wq : Wv;
    const float* bias = (which == 0) ? bk : (which == 1) ? bq : bv;

    __shared__ float As[BK][SMW];
    __shared__ float Bs[BK][SMW];

    const int m0 = blockIdx.x * BM;   // l
    const int n0 = blockIdx.y * BN;   // o
    const float* Hb = H + (size_t)b * D * L;

    const int tid = threadIdx.x;
    const int tx = tid % 16;
    const int ty = tid / 16;

    float acc[8][8];
    #pragma unroll
    for (int i = 0; i < 8; i++)
        #pragma unroll
        for (int j = 0; j < 8; j++) acc[i][j] = 0.0f;

    for (int k0 = 0; k0 < D; k0 += BK) {
        {
            int i = tid >> 5;
            int l = (tid & 31) << 2;
            float4 v = *(const float4*)(Hb + (size_t)(k0 + i) * L + m0 + l);
            *(float4*)(&As[i][l]) = v;
        }
        {
            int o = tid >> 1;
            int i = (tid & 1) << 2;
            float4 v = *(const float4*)(W + (size_t)(n0 + o) * D + k0 + i);
            Bs[i + 0][o] = v.x; Bs[i + 1][o] = v.y;
            Bs[i + 2][o] = v.z; Bs[i + 3][o] = v.w;
        }
        __syncthreads();
        #pragma unroll
        for (int k = 0; k < BK; k++) {
            float a[8], bb[8];
            *(float4*)&a[0]  = *(float4*)&As[k][ty * 4];
            *(float4*)&a[4]  = *(float4*)&As[k][64 + ty * 4];
            *(float4*)&bb[0] = *(float4*)&Bs[k][tx * 4];
            *(float4*)&bb[4] = *(float4*)&Bs[k][64 + tx * 4];
            #pragma unroll
            for (int i = 0; i < 8; i++)
                #pragma unroll
                for (int j = 0; j < 8; j++)
                    acc[i][j] = fmaf(a[i], bb[j], acc[i][j]);
        }
        __syncthreads();
    }

    if (which <= 1) {
        __nv_bfloat16* hi = (which == 0 ? gKh : gQh) + (size_t)b * L * D;
        __nv_bfloat16* lo = (which == 0 ? gKl : gQl) + (size_t)b * L * D;
        #pragma unroll
        for (int i = 0; i < 8; i++) {
            int l = m0 + (i / 4) * 64 + ty * 4 + (i % 4);
            int o0 = n0 + tx * 4;
            int o1 = n0 + 64 + tx * 4;
            float f0[4], f1[4];
            #pragma unroll
            for (int j = 0; j < 4; j++) f0[j] = elu_f(acc[i][j]     + bias[o0 + j]);
            #pragma unroll
            for (int j = 0; j < 4; j++) f1[j] = elu_f(acc[i][4 + j] + bias[o1 + j]);
            split4(f0, hi + (size_t)l * D + o0, lo + (size_t)l * D + o0);
            split4(f1, hi + (size_t)l * D + o1, lo + (size_t)l * D + o1);
        }
    } else {
        __nv_bfloat16* hi = gVth + (size_t)b * D * L;
        __nv_bfloat16* lo = gVtl + (size_t)b * D * L;
        int l0 = m0 + ty * 4;
        #pragma unroll
        for (int j = 0; j < 8; j++) {
            int o = n0 + ((j < 4) ? (tx * 4 + j) : (64 + tx * 4 + (j - 4)));
            float bo = bias[o];
            float f0[4], f1[4];
            #pragma unroll
            for (int i = 0; i < 4; i++) f0[i] = elu_f(acc[i][j]     + bo);
            #pragma unroll
            for (int i = 0; i < 4; i++) f1[i] = elu_f(acc[4 + i][j] + bo);
            split4(f0, hi + (size_t)o * L + l0,      lo + (size_t)o * L + l0);
            split4(f1, hi + (size_t)o * L + l0 + 64, lo + (size_t)o * L + l0 + 64);
        }
    }
}

// ---------------------------------------------------------------------------
// Row softmax over last dim (L=2048), in place + bf16 hi/lo split output.
// ---------------------------------------------------------------------------
__global__ __launch_bounds__(256) void softmax_kernel(float* __restrict__ A)
{
    __shared__ float red[256];
    const size_t base = (size_t)blockIdx.x * L;
    float* row = A + base;
    const int tid = threadIdx.x;

    float v[8];
    float m = -INFINITY;
    #pragma unroll
    for (int j = 0; j < 8; j++) {
        v[j] = row[tid + j * 256];
        m = fmaxf(m, v[j]);
    }
    red[tid] = m;
    __syncthreads();
    #pragma unroll
    for (int s = 128; s > 0; s >>= 1) {
        if (tid < s) red[tid] = fmaxf(red[tid], red[tid + s]);
        __syncthreads();
    }
    m = red[0];
    __syncthreads();

    float sum = 0.0f;
    #pragma unroll
    for (int j = 0; j < 8; j++) {
        v[j] = expf(v[j] - m);
        sum += v[j];
    }
    red[tid] = sum;
    __syncthreads();
    #pragma unroll
    for (int s = 128; s > 0; s >>= 1) {
        if (tid < s) red[tid] += red[tid + s];
        __syncthreads();
    }
    float inv = 1.0f / red[0];
    #pragma unroll
    for (int j = 0; j < 8; j++) {
        int idx = tid + j * 256;
        float a = v[j] * inv;
        row[idx] = a;
        __nv_bfloat16 h = __float2bfloat16(a);
        gAh[base + idx] = h;
        gAl[base + idx] = __float2bfloat16(a - __bfloat162float(h));
    }
}

// ---------------------------------------------------------------------------
extern "C" void kernel_launch(void* const* d_in, const int* in_sizes, int n_in,
                              void* d_out, int out_size)
{
    const float* H  = (const float*)d_in[0];
    const float* Wk = (const float*)d_in[1];
    const float* bk = (const float*)d_in[2];
    const float* Wq = (const float*)d_in[3];
    const float* bq = (const float*)d_in[4];
    const float* Wv = (const float*)d_in[5];
    const float* bv = (const float*)d_in[6];

    float* C_out = (float*)d_out;                    // [B, L, D]
    float* A_out = C_out + (size_t)B * L * D;        // [B, L, L]

    cudaFuncSetAttribute(mm3_kernel, cudaFuncAttributeMaxDynamicSharedMemorySize,
                         MM3_SMEM);

    // 1) projections -> split bf16 Q, K (row-major) and V^T (transposed)
    {
        dim3 grid(L / BM, D / BN, B * 3);
        proj_kernel<<<grid, 256>>>(H, Wk, bk, Wq, bq, Wv, bv);
    }

    // 2) E = scale * Q K^T  (written to A_out region)
    {
        __nv_bfloat16 *qh, *ql, *kh, *kl;
        cudaGetSymbolAddress((void**)&qh, gQh);
        cudaGetSymbolAddress((void**)&ql, gQl);
        cudaGetSymbolAddress((void**)&kh, gKh);
        cudaGetSymbolAddress((void**)&kl, gKl);
        dim3 grid(L / 128, L / 128, B);
        mm3_kernel<<<grid, 256, MM3_SMEM>>>(
            qh, ql, (size_t)L * D, D,
            kh, kl, (size_t)L * D, D,
            A_out, (size_t)L * L, L,
            D / 32, 0.044194173824159216f);
    }

    // 3) softmax rows (fp32 in place) + split bf16 A
    softmax_kernel<<<B * L, 256>>>(A_out);

    // 4) C = A V   (A split @ [q,k] K-major; V^T split @ [d,k] K-major)
    {
        __nv_bfloat16 *ah, *al, *vh, *vl;
        cudaGetSymbolAddress((void**)&ah, gAh);
        cudaGetSymbolAddress((void**)&al, gAl);
        cudaGetSymbolAddress((void**)&vh, gVth);
        cudaGetSymbolAddress((void**)&vl, gVtl);
        dim3 grid(L / 128, D / 128, B);
        mm3_kernel<<<grid, 256, MM3_SMEM>>>(
            ah, al, (size_t)L * L, L,
            vh, vl, (size_t)D * L, L,
            C_out, (size_t)L * D, D,
            L / 32, 1.0f);
    }
}

// round 4
// speedup vs baseline: 1.7285x; 1.1488x over previous
#include <cuda_runtime.h>
#include <cuda_bf16.h>
#include <math.h>
#include <stdint.h>

#define B 8
#define D 512
#define L 2048
#define DD (512*512)

#define BLD (8u*2048u*512u)            // 8388608
#define BLL (8ull*2048ull*2048ull)     // 33554432

// bf16 hi/lo split operands
__device__ __align__(128) __nv_bfloat16 gQh[BLD], gQl[BLD];
__device__ __align__(128) __nv_bfloat16 gKh[BLD], gKl[BLD];
__device__ __align__(128) __nv_bfloat16 gVth[BLD], gVtl[BLD];   // V^T: [b][d][l]
__device__ __align__(128) __nv_bfloat16 gAh[BLL], gAl[BLL];
__device__ __align__(128) __nv_bfloat16 gHth[BLD], gHtl[BLD];   // H^T: [b][l][i]
__device__ __align__(128) __nv_bfloat16 gWh[3*DD], gWl[3*DD];   // [Wk,Wq,Wv][o][i]

// ---------------------------------------------------------------------------
__device__ __forceinline__ uint32_t smem_u32(const void* p) {
    uint32_t a;
    asm("{ .reg .u64 t; cvta.to.shared.u64 t, %1; cvt.u32.u64 %0, t; }"
        : "=r"(a) : "l"(p));
    return a;
}

__device__ __forceinline__ void ldsm_x4(uint32_t* r, uint32_t addr) {
    asm volatile("ldmatrix.sync.aligned.m8n8.x4.shared.b16 {%0,%1,%2,%3}, [%4];"
        : "=r"(r[0]), "=r"(r[1]), "=r"(r[2]), "=r"(r[3]) : "r"(addr));
}

__device__ __forceinline__ void mma_bf16(float* c, const uint32_t* a, const uint32_t* b) {
    asm volatile(
        "mma.sync.aligned.m16n8k16.row.col.f32.bf16.bf16.f32 "
        "{%0,%1,%2,%3}, {%4,%5,%6,%7}, {%8,%9}, {%0,%1,%2,%3};"
        : "+f"(c[0]), "+f"(c[1]), "+f"(c[2]), "+f"(c[3])
        : "r"(a[0]), "r"(a[1]), "r"(a[2]), "r"(a[3]), "r"(b[0]), "r"(b[1]));
}

__device__ __forceinline__ void cp16(uint32_t saddr, const void* gaddr) {
    asm volatile("cp.async.cg.shared.global [%0], [%1], 16;"
        :: "r"(saddr), "l"(gaddr) : "memory");
}
#define CP_COMMIT() asm volatile("cp.async.commit_group;" ::: "memory")
#define CP_WAIT1()  asm volatile("cp.async.wait_group 1;" ::: "memory")
#define CP_WAIT0()  asm volatile("cp.async.wait_group 0;" ::: "memory")

__device__ __forceinline__ float elu_f(float x) {
    return x > 0.0f ? x : expm1f(x);
}

__device__ __forceinline__ void split_store2(float f0, float f1,
                                             __nv_bfloat16* hi, __nv_bfloat16* lo)
{
    __nv_bfloat162 h, l;
    h.x = __float2bfloat16(f0);
    h.y = __float2bfloat16(f1);
    l.x = __float2bfloat16(f0 - __bfloat162float(h.x));
    l.y = __float2bfloat16(f1 - __bfloat162float(h.y));
    *(__nv_bfloat162*)hi = h;
    *(__nv_bfloat162*)lo = l;
}

// ---------------------------------------------------------------------------
// 3-way split GEMM: acc[m,n] = sum_k (Ah+Al)[m,k]*(Bh+Bl)[n,k]  (hh+hl+lh)
// CTA tile 128x128, K-chunk 32. 8 warps = (wm 0..3)x(wn 0..1), 32x64 each.
// EPI 0: Cout = scale*acc (fp32)
// EPI 1: split(elu(acc + bias[col])) -> Oh/Ol
// EPI 2: split(elu(acc + bias[row])) -> Oh/Ol
// ---------------------------------------------------------------------------
#define ROWB  80
#define TILEB (128 * ROWB)          // 10240
#define STAGEB (4 * TILEB)          // 40960
#define MM3_SMEM (2 * STAGEB)       // 81920

template<int EPI>
__global__ __launch_bounds__(256, 1) void mm3_kernel(
    const __nv_bfloat16* __restrict__ Ah, const __nv_bfloat16* __restrict__ Al,
    size_t sA, int ldA,
    const __nv_bfloat16* __restrict__ Bh, const __nv_bfloat16* __restrict__ Bl,
    size_t sB, int ldB,
    float* __restrict__ Cout,
    __nv_bfloat16* __restrict__ Oh, __nv_bfloat16* __restrict__ Ol,
    const float* __restrict__ bias,
    size_t sC, int ldC,
    int nchunks, float scale)
{
    extern __shared__ char smem[];
    const uint32_t sbase = smem_u32(smem);
    const int tid = threadIdx.x, wid = tid >> 5, lane = tid & 31;
    const int wm = wid & 3, wn = wid >> 2;
    const int m0 = blockIdx.x * 128, n0 = blockIdx.y * 128, bz = blockIdx.z;

    const __nv_bfloat16* srcA_h = Ah + (size_t)bz * sA + (size_t)m0 * ldA;
    const __nv_bfloat16* srcA_l = Al + (size_t)bz * sA + (size_t)m0 * ldA;
    const __nv_bfloat16* srcB_h = Bh + (size_t)bz * sB + (size_t)n0 * ldB;
    const __nv_bfloat16* srcB_l = Bl + (size_t)bz * sB + (size_t)n0 * ldB;

    const int r0i = (tid * 2) >> 2,      s0i = (tid * 2) & 3;
    const int r1i = (tid * 2 + 1) >> 2,  s1i = (tid * 2 + 1) & 3;

#define ISSUE_CHUNK(ch) do { \
        const int _k0 = (ch) * 32; \
        const uint32_t _sb = sbase + ((ch) & 1) * STAGEB; \
        cp16(_sb + 0*TILEB + r0i*ROWB + s0i*16, srcA_h + (size_t)r0i*ldA + _k0 + s0i*8); \
        cp16(_sb + 0*TILEB + r1i*ROWB + s1i*16, srcA_h + (size_t)r1i*ldA + _k0 + s1i*8); \
        cp16(_sb + 1*TILEB + r0i*ROWB + s0i*16, srcA_l + (size_t)r0i*ldA + _k0 + s0i*8); \
        cp16(_sb + 1*TILEB + r1i*ROWB + s1i*16, srcA_l + (size_t)r1i*ldA + _k0 + s1i*8); \
        cp16(_sb + 2*TILEB + r0i*ROWB + s0i*16, srcB_h + (size_t)r0i*ldB + _k0 + s0i*8); \
        cp16(_sb + 2*TILEB + r1i*ROWB + s1i*16, srcB_h + (size_t)r1i*ldB + _k0 + s1i*8); \
        cp16(_sb + 3*TILEB + r0i*ROWB + s0i*16, srcB_l + (size_t)r0i*ldB + _k0 + s0i*8); \
        cp16(_sb + 3*TILEB + r1i*ROWB + s1i*16, srcB_l + (size_t)r1i*ldB + _k0 + s1i*8); \
        CP_COMMIT(); \
    } while (0)

    float acc[2][8][4];
    #pragma unroll
    for (int i = 0; i < 2; i++)
        #pragma unroll
        for (int j = 0; j < 8; j++)
            #pragma unroll
            for (int t = 0; t < 4; t++) acc[i][j][t] = 0.0f;

    const int rowA_l = lane & 15;
    const uint32_t offA_l = (uint32_t)rowA_l * ROWB + (lane >> 4) * 16;
    const int rowB_l = (lane & 7) + ((lane & 16) ? 8 : 0);
    const uint32_t offB_l = (uint32_t)rowB_l * ROWB + ((lane & 8) ? 16 : 0);

    ISSUE_CHUNK(0);

    for (int ch = 0; ch < nchunks; ch++) {
        if (ch + 1 < nchunks) { ISSUE_CHUNK(ch + 1); CP_WAIT1(); }
        else                  { CP_WAIT0(); }
        __syncthreads();

        const uint32_t sb = sbase + (ch & 1) * STAGEB;
        #pragma unroll
        for (int ks = 0; ks < 2; ks++) {
            const uint32_t kb = ks * 32;
            uint32_t ah[2][4], al[2][4], bh[4][4], bl[4][4];
            #pragma unroll
            for (int i = 0; i < 2; i++) {
                uint32_t base = sb + (uint32_t)(wm * 32 + i * 16) * ROWB + kb;
                ldsm_x4(ah[i], base + 0*TILEB + offA_l);
                ldsm_x4(al[i], base + 1*TILEB + offA_l);
            }
            #pragma unroll
            for (int j2 = 0; j2 < 4; j2++) {
                uint32_t base = sb + (uint32_t)(wn * 64 + j2 * 16) * ROWB + kb;
                ldsm_x4(bh[j2], base + 2*TILEB + offB_l);
                ldsm_x4(bl[j2], base + 3*TILEB + offB_l);
            }
            // 3 passes: hh, hl, lh — 16 independent MMAs between same-acc reuses
            #pragma unroll
            for (int p = 0; p < 3; p++) {
                #pragma unroll
                for (int i = 0; i < 2; i++)
                    #pragma unroll
                    for (int j = 0; j < 8; j++) {
                        const uint32_t* ap = (p == 2) ? al[i] : ah[i];
                        const uint32_t* bp = (p == 1) ? &bl[j >> 1][(j & 1) * 2]
                                                      : &bh[j >> 1][(j & 1) * 2];
                        mma_bf16(acc[i][j], ap, bp);
                    }
            }
        }
        __syncthreads();
    }
#undef ISSUE_CHUNK

    // epilogue
    const int g = lane >> 2, tg = lane & 3;
    #pragma unroll
    for (int i = 0; i < 2; i++) {
        const int r0 = m0 + wm * 32 + i * 16 + g;
        #pragma unroll
        for (int j = 0; j < 8; j++) {
            const int c = n0 + wn * 64 + j * 8 + tg * 2;
            if (EPI == 0) {
                float* dst = Cout + (size_t)bz * sC;
                float2 v0 = make_float2(acc[i][j][0] * scale, acc[i][j][1] * scale);
                float2 v1 = make_float2(acc[i][j][2] * scale, acc[i][j][3] * scale);
                *(float2*)(dst + (size_t)r0 * ldC + c) = v0;
                *(float2*)(dst + (size_t)(r0 + 8) * ldC + c) = v1;
            } else {
                __nv_bfloat16* oh = Oh + (size_t)bz * sC;
                __nv_bfloat16* ol = Ol + (size_t)bz * sC;
                float f00, f01, f10, f11;
                if (EPI == 1) {
                    float b0 = bias[c], b1 = bias[c + 1];
                    f00 = elu_f(acc[i][j][0] + b0);
                    f01 = elu_f(acc[i][j][1] + b1);
                    f10 = elu_f(acc[i][j][2] + b0);
                    f11 = elu_f(acc[i][j][3] + b1);
                } else {
                    float b0 = bias[r0], b1 = bias[r0 + 8];
                    f00 = elu_f(acc[i][j][0] + b0);
                    f01 = elu_f(acc[i][j][1] + b0);
                    f10 = elu_f(acc[i][j][2] + b1);
                    f11 = elu_f(acc[i][j][3] + b1);
                }
                split_store2(f00, f01, oh + (size_t)r0 * ldC + c,
                                       ol + (size_t)r0 * ldC + c);
                split_store2(f10, f11, oh + (size_t)(r0 + 8) * ldC + c,
                                       ol + (size_t)(r0 + 8) * ldC + c);
            }
        }
    }
}

// ---------------------------------------------------------------------------
// H^T split: H[b][i][l] fp32 -> gHth/gHtl [b][l][i] bf16 hi/lo
// grid (L/32, D/32, B), 256 threads
// ---------------------------------------------------------------------------
__global__ __launch_bounds__(256) void hsplit_kernel(const float* __restrict__ H)
{
    __shared__ float t[32][33];
    const int b = blockIdx.z;
    const int l0 = blockIdx.x * 32, i0 = blockIdx.y * 32;
    const int tx = threadIdx.x & 31, ty = threadIdx.x >> 5;

    const float* Hb = H + ((size_t)b * D + i0) * L + l0;
    #pragma unroll
    for (int r = 0; r < 4; r++)
        t[ty + 8 * r][tx] = Hb[(size_t)(ty + 8 * r) * L + tx];
    __syncthreads();

    #pragma unroll
    for (int r = 0; r < 4; r++) {
        float v = t[tx][ty + 8 * r];
        size_t idx = ((size_t)b * L + l0 + ty + 8 * r) * D + i0 + tx;
        __nv_bfloat16 h = __float2bfloat16(v);
        gHth[idx] = h;
        gHtl[idx] = __float2bfloat16(v - __bfloat162float(h));
    }
}

// ---------------------------------------------------------------------------
// W split: [Wk, Wq, Wv] fp32 -> gWh/gWl bf16 hi/lo
// ---------------------------------------------------------------------------
__global__ __launch_bounds__(256) void wsplit_kernel(
    const float* __restrict__ Wk, const float* __restrict__ Wq,
    const float* __restrict__ Wv)
{
    int idx = blockIdx.x * 256 + threadIdx.x;
    if (idx >= 3 * DD) return;
    int which = idx / DD, off = idx % DD;
    const float* W = (which == 0) ? Wk : (which == 1) ? Wq : Wv;
    float v = W[off];
    __nv_bfloat16 h = __float2bfloat16(v);
    gWh[idx] = h;
    gWl[idx] = __float2bfloat16(v - __bfloat162float(h));
}

// ---------------------------------------------------------------------------
// Row softmax over last dim (L=2048), in place + bf16 hi/lo split output.
// ---------------------------------------------------------------------------
__global__ __launch_bounds__(256) void softmax_kernel(float* __restrict__ A)
{
    __shared__ float red[256];
    const size_t base = (size_t)blockIdx.x * L;
    float* row = A + base;
    const int tid = threadIdx.x;

    float v[8];
    float m = -INFINITY;
    #pragma unroll
    for (int j = 0; j < 8; j++) {
        v[j] = row[tid + j * 256];
        m = fmaxf(m, v[j]);
    }
    red[tid] = m;
    __syncthreads();
    #pragma unroll
    for (int s = 128; s > 0; s >>= 1) {
        if (tid < s) red[tid] = fmaxf(red[tid], red[tid + s]);
        __syncthreads();
    }
    m = red[0];
    __syncthreads();

    float sum = 0.0f;
    #pragma unroll
    for (int j = 0; j < 8; j++) {
        v[j] = expf(v[j] - m);
        sum += v[j];
    }
    red[tid] = sum;
    __syncthreads();
    #pragma unroll
    for (int s = 128; s > 0; s >>= 1) {
        if (tid < s) red[tid] += red[tid + s];
        __syncthreads();
    }
    float inv = 1.0f / red[0];
    #pragma unroll
    for (int j = 0; j < 8; j++) {
        int idx = tid + j * 256;
        float a = v[j] * inv;
        row[idx] = a;
        __nv_bfloat16 h = __float2bfloat16(a);
        gAh[base + idx] = h;
        gAl[base + idx] = __float2bfloat16(a - __bfloat162float(h));
    }
}

// ---------------------------------------------------------------------------
extern "C" void kernel_launch(void* const* d_in, const int* in_sizes, int n_in,
                              void* d_out, int out_size)
{
    const float* H  = (const float*)d_in[0];
    const float* Wk = (const float*)d_in[1];
    const float* bk = (const float*)d_in[2];
    const float* Wq = (const float*)d_in[3];
    const float* bq = (const float*)d_in[4];
    const float* Wv = (const float*)d_in[5];
    const float* bv = (const float*)d_in[6];

    float* C_out = (float*)d_out;                    // [B, L, D]
    float* A_out = C_out + (size_t)B * L * D;        // [B, L, L]

    cudaFuncSetAttribute(mm3_kernel<0>, cudaFuncAttributeMaxDynamicSharedMemorySize, MM3_SMEM);
    cudaFuncSetAttribute(mm3_kernel<1>, cudaFuncAttributeMaxDynamicSharedMemorySize, MM3_SMEM);
    cudaFuncSetAttribute(mm3_kernel<2>, cudaFuncAttributeMaxDynamicSharedMemorySize, MM3_SMEM);

    __nv_bfloat16 *qh, *ql, *kh, *kl, *vh, *vl, *ah, *al, *hth, *htl, *wh, *wl;
    cudaGetSymbolAddress((void**)&qh, gQh);   cudaGetSymbolAddress((void**)&ql, gQl);
    cudaGetSymbolAddress((void**)&kh, gKh);   cudaGetSymbolAddress((void**)&kl, gKl);
    cudaGetSymbolAddress((void**)&vh, gVth);  cudaGetSymbolAddress((void**)&vl, gVtl);
    cudaGetSymbolAddress((void**)&ah, gAh);   cudaGetSymbolAddress((void**)&al, gAl);
    cudaGetSymbolAddress((void**)&hth, gHth); cudaGetSymbolAddress((void**)&htl, gHtl);
    cudaGetSymbolAddress((void**)&wh, gWh);   cudaGetSymbolAddress((void**)&wl, gWl);

    // 0) splits
    wsplit_kernel<<<(3 * DD + 255) / 256, 256>>>(Wk, Wq, Wv);
    {
        dim3 grid(L / 32, D / 32, B);
        hsplit_kernel<<<grid, 256>>>(H);
    }

    // 1) Q = elu(Ht Wq^T + bq): A=Ht rows l, B=Wq rows o -> [l][o]
    {
        dim3 grid(L / 128, D / 128, B);
        mm3_kernel<1><<<grid, 256, MM3_SMEM>>>(
            hth, htl, (size_t)L * D, D,
            wh + 1 * DD, wl + 1 * DD, 0, D,
            nullptr, qh, ql, bq, (size_t)L * D, D,
            D / 32, 1.0f);
        mm3_kernel<1><<<grid, 256, MM3_SMEM>>>(
            hth, htl, (size_t)L * D, D,
            wh + 0 * DD, wl + 0 * DD, 0, D,
            nullptr, kh, kl, bk, (size_t)L * D, D,
            D / 32, 1.0f);
    }
    // V^T = elu(Wv Ht^T + bv[row]): A=Wv rows o, B=Ht rows l -> [o][l]
    {
        dim3 grid(D / 128, L / 128, B);
        mm3_kernel<2><<<grid, 256, MM3_SMEM>>>(
            wh + 2 * DD, wl + 2 * DD, 0, D,
            hth, htl, (size_t)L * D, D,
            nullptr, vh, vl, bv, (size_t)D * L, L,
            D / 32, 1.0f);
    }

    // 2) E = scale * Q K^T
    {
        dim3 grid(L / 128, L / 128, B);
        mm3_kernel<0><<<grid, 256, MM3_SMEM>>>(
            qh, ql, (size_t)L * D, D,
            kh, kl, (size_t)L * D, D,
            A_out, nullptr, nullptr, nullptr, (size_t)L * L, L,
            D / 32, 0.044194173824159216f);
    }

    // 3) softmax rows + split bf16 A
    softmax_kernel<<<B * L, 256>>>(A_out);

    // 4) C = A V
    {
        dim3 grid(L / 128, D / 128, B);
        mm3_kernel<0><<<grid, 256, MM3_SMEM>>>(
            ah, al, (size_t)L * L, L,
            vh, vl, (size_t)D * L, L,
            C_out, nullptr, nullptr, nullptr, (size_t)L * D, D,
            L / 32, 1.0f);
    }
}

// round 5
// speedup vs baseline: 2.0819x; 1.2045x over previous
#include <cuda_runtime.h>
#include <cuda_bf16.h>
#include <math.h>
#include <stdint.h>

#define B 8
#define D 512
#define L 2048
#define DD (512*512)

#define BLD (8u*2048u*512u)            // 8388608
#define BLL (8ull*2048ull*2048ull)     // 33554432

// bf16 hi/lo split operands
__device__ __align__(128) __nv_bfloat16 gQh[BLD], gQl[BLD];
__device__ __align__(128) __nv_bfloat16 gKh[BLD], gKl[BLD];
__device__ __align__(128) __nv_bfloat16 gVth[BLD], gVtl[BLD];   // V^T: [b][d][l]
__device__ __align__(128) __nv_bfloat16 gAh[BLL], gAl[BLL];
__device__ __align__(128) __nv_bfloat16 gHth[BLD], gHtl[BLD];   // H^T: [b][l][i]
__device__ __align__(128) __nv_bfloat16 gWh[3*DD], gWl[3*DD];   // [Wk,Wq,Wv][o][i]

// ---------------------------------------------------------------------------
__device__ __forceinline__ uint32_t smem_u32(const void* p) {
    uint32_t a;
    asm("{ .reg .u64 t; cvta.to.shared.u64 t, %1; cvt.u32.u64 %0, t; }"
        : "=r"(a) : "l"(p));
    return a;
}

__device__ __forceinline__ void ldsm_x4(uint32_t* r, uint32_t addr) {
    asm volatile("ldmatrix.sync.aligned.m8n8.x4.shared.b16 {%0,%1,%2,%3}, [%4];"
        : "=r"(r[0]), "=r"(r[1]), "=r"(r[2]), "=r"(r[3]) : "r"(addr));
}

__device__ __forceinline__ void mma_bf16(float* c, const uint32_t* a, const uint32_t* b) {
    asm volatile(
        "mma.sync.aligned.m16n8k16.row.col.f32.bf16.bf16.f32 "
        "{%0,%1,%2,%3}, {%4,%5,%6,%7}, {%8,%9}, {%0,%1,%2,%3};"
        : "+f"(c[0]), "+f"(c[1]), "+f"(c[2]), "+f"(c[3])
        : "r"(a[0]), "r"(a[1]), "r"(a[2]), "r"(a[3]), "r"(b[0]), "r"(b[1]));
}

__device__ __forceinline__ void cp16(uint32_t saddr, const void* gaddr) {
    asm volatile("cp.async.cg.shared.global [%0], [%1], 16;"
        :: "r"(saddr), "l"(gaddr) : "memory");
}
#define CP_COMMIT() asm volatile("cp.async.commit_group;" ::: "memory")
#define CP_WAIT1()  asm volatile("cp.async.wait_group 1;" ::: "memory")
#define CP_WAIT0()  asm volatile("cp.async.wait_group 0;" ::: "memory")

__device__ __forceinline__ float elu_f(float x) {
    return x > 0.0f ? x : expm1f(x);
}

__device__ __forceinline__ void split_store2(float f0, float f1,
                                             __nv_bfloat16* hi, __nv_bfloat16* lo)
{
    __nv_bfloat162 h, l;
    h.x = __float2bfloat16(f0);
    h.y = __float2bfloat16(f1);
    l.x = __float2bfloat16(f0 - __bfloat162float(h.x));
    l.y = __float2bfloat16(f1 - __bfloat162float(h.y));
    *(__nv_bfloat162*)hi = h;
    *(__nv_bfloat162*)lo = l;
}

// ---------------------------------------------------------------------------
// 3-way split GEMM: acc[m,n] = sum_k (Ah+Al)[m,k]*(Bh+Bl)[n,k]  (hh+hl+lh)
// CTA tile 128x128, K-chunk 32. 8 warps = (wm 0..3)x(wn 0..1), 32x64 each.
// 2 CTAs/SM (reg budget 128): B fragments processed in 2 halves.
// EPI 0: Cout = scale*acc (fp32)
// EPI 1: split(elu(acc + bias[col])) -> Oh/Ol
// EPI 2: split(elu(acc + bias[row])) -> Oh/Ol
// ---------------------------------------------------------------------------
#define ROWB  80
#define TILEB (128 * ROWB)          // 10240
#define STAGEB (4 * TILEB)          // 40960
#define MM3_SMEM (2 * STAGEB)       // 81920

template<int EPI>
__global__ __launch_bounds__(256, 2) void mm3_kernel(
    const __nv_bfloat16* __restrict__ Ah, const __nv_bfloat16* __restrict__ Al,
    size_t sA, int ldA,
    const __nv_bfloat16* __restrict__ Bh, const __nv_bfloat16* __restrict__ Bl,
    size_t sB, int ldB,
    float* __restrict__ Cout,
    __nv_bfloat16* __restrict__ Oh, __nv_bfloat16* __restrict__ Ol,
    const float* __restrict__ bias,
    size_t sC, int ldC,
    int nchunks, float scale)
{
    extern __shared__ char smem[];
    const uint32_t sbase = smem_u32(smem);
    const int tid = threadIdx.x, wid = tid >> 5, lane = tid & 31;
    const int wm = wid & 3, wn = wid >> 2;
    const int m0 = blockIdx.x * 128, n0 = blockIdx.y * 128, bz = blockIdx.z;

    const __nv_bfloat16* srcA_h = Ah + (size_t)bz * sA + (size_t)m0 * ldA;
    const __nv_bfloat16* srcA_l = Al + (size_t)bz * sA + (size_t)m0 * ldA;
    const __nv_bfloat16* srcB_h = Bh + (size_t)bz * sB + (size_t)n0 * ldB;
    const __nv_bfloat16* srcB_l = Bl + (size_t)bz * sB + (size_t)n0 * ldB;

    const int r0i = (tid * 2) >> 2,      s0i = (tid * 2) & 3;
    const int r1i = (tid * 2 + 1) >> 2,  s1i = (tid * 2 + 1) & 3;

#define ISSUE_CHUNK(ch) do { \
        const int _k0 = (ch) * 32; \
        const uint32_t _sb = sbase + ((ch) & 1) * STAGEB; \
        cp16(_sb + 0*TILEB + r0i*ROWB + s0i*16, srcA_h + (size_t)r0i*ldA + _k0 + s0i*8); \
        cp16(_sb + 0*TILEB + r1i*ROWB + s1i*16, srcA_h + (size_t)r1i*ldA + _k0 + s1i*8); \
        cp16(_sb + 1*TILEB + r0i*ROWB + s0i*16, srcA_l + (size_t)r0i*ldA + _k0 + s0i*8); \
        cp16(_sb + 1*TILEB + r1i*ROWB + s1i*16, srcA_l + (size_t)r1i*ldA + _k0 + s1i*8); \
        cp16(_sb + 2*TILEB + r0i*ROWB + s0i*16, srcB_h + (size_t)r0i*ldB + _k0 + s0i*8); \
        cp16(_sb + 2*TILEB + r1i*ROWB + s1i*16, srcB_h + (size_t)r1i*ldB + _k0 + s1i*8); \
        cp16(_sb + 3*TILEB + r0i*ROWB + s0i*16, srcB_l + (size_t)r0i*ldB + _k0 + s0i*8); \
        cp16(_sb + 3*TILEB + r1i*ROWB + s1i*16, srcB_l + (size_t)r1i*ldB + _k0 + s1i*8); \
        CP_COMMIT(); \
    } while (0)

    float acc[2][8][4];
    #pragma unroll
    for (int i = 0; i < 2; i++)
        #pragma unroll
        for (int j = 0; j < 8; j++)
            #pragma unroll
            for (int t = 0; t < 4; t++) acc[i][j][t] = 0.0f;

    const int rowA_l = lane & 15;
    const uint32_t offA_l = (uint32_t)rowA_l * ROWB + (lane >> 4) * 16;
    const int rowB_l = (lane & 7) + ((lane & 16) ? 8 : 0);
    const uint32_t offB_l = (uint32_t)rowB_l * ROWB + ((lane & 8) ? 16 : 0);

    ISSUE_CHUNK(0);

    for (int ch = 0; ch < nchunks; ch++) {
        if (ch + 1 < nchunks) { ISSUE_CHUNK(ch + 1); CP_WAIT1(); }
        else                  { CP_WAIT0(); }
        __syncthreads();

        const uint32_t sb = sbase + (ch & 1) * STAGEB;
        #pragma unroll
        for (int ks = 0; ks < 2; ks++) {
            const uint32_t kb = ks * 32;
            uint32_t ah[2][4], al[2][4];
            #pragma unroll
            for (int i = 0; i < 2; i++) {
                uint32_t base = sb + (uint32_t)(wm * 32 + i * 16) * ROWB + kb;
                ldsm_x4(ah[i], base + 0*TILEB + offA_l);
                ldsm_x4(al[i], base + 1*TILEB + offA_l);
            }
            // Process B in 2 halves of 32 cols to halve live fragment regs
            #pragma unroll
            for (int half = 0; half < 2; half++) {
                uint32_t bh[2][4], bl[2][4];
                #pragma unroll
                for (int j2 = 0; j2 < 2; j2++) {
                    uint32_t base = sb +
                        (uint32_t)(wn * 64 + (half * 2 + j2) * 16) * ROWB + kb;
                    ldsm_x4(bh[j2], base + 2*TILEB + offB_l);
                    ldsm_x4(bl[j2], base + 3*TILEB + offB_l);
                }
                // 3 passes (hh, hl, lh): 8 independent MMAs between acc reuses
                #pragma unroll
                for (int p = 0; p < 3; p++) {
                    #pragma unroll
                    for (int i = 0; i < 2; i++)
                        #pragma unroll
                        for (int j = 0; j < 4; j++) {
                            const uint32_t* ap = (p == 2) ? al[i] : ah[i];
                            const uint32_t* bp = (p == 1)
                                ? &bl[j >> 1][(j & 1) * 2]
                                : &bh[j >> 1][(j & 1) * 2];
                            mma_bf16(acc[i][half * 4 + j], ap, bp);
                        }
                }
            }
        }
        __syncthreads();
    }
#undef ISSUE_CHUNK

    // epilogue
    const int g = lane >> 2, tg = lane & 3;
    #pragma unroll
    for (int i = 0; i < 2; i++) {
        const int r0 = m0 + wm * 32 + i * 16 + g;
        #pragma unroll
        for (int j = 0; j < 8; j++) {
            const int c = n0 + wn * 64 + j * 8 + tg * 2;
            if (EPI == 0) {
                float* dst = Cout + (size_t)bz * sC;
                float2 v0 = make_float2(acc[i][j][0] * scale, acc[i][j][1] * scale);
                float2 v1 = make_float2(acc[i][j][2] * scale, acc[i][j][3] * scale);
                *(float2*)(dst + (size_t)r0 * ldC + c) = v0;
                *(float2*)(dst + (size_t)(r0 + 8) * ldC + c) = v1;
            } else {
                __nv_bfloat16* oh = Oh + (size_t)bz * sC;
                __nv_bfloat16* ol = Ol + (size_t)bz * sC;
                float f00, f01, f10, f11;
                if (EPI == 1) {
                    float b0 = bias[c], b1 = bias[c + 1];
                    f00 = elu_f(acc[i][j][0] + b0);
                    f01 = elu_f(acc[i][j][1] + b1);
                    f10 = elu_f(acc[i][j][2] + b0);
                    f11 = elu_f(acc[i][j][3] + b1);
                } else {
                    float b0 = bias[r0], b1 = bias[r0 + 8];
                    f00 = elu_f(acc[i][j][0] + b0);
                    f01 = elu_f(acc[i][j][1] + b0);
                    f10 = elu_f(acc[i][j][2] + b1);
                    f11 = elu_f(acc[i][j][3] + b1);
                }
                split_store2(f00, f01, oh + (size_t)r0 * ldC + c,
                                       ol + (size_t)r0 * ldC + c);
                split_store2(f10, f11, oh + (size_t)(r0 + 8) * ldC + c,
                                       ol + (size_t)(r0 + 8) * ldC + c);
            }
        }
    }
}

// ---------------------------------------------------------------------------
// H^T split: H[b][i][l] fp32 -> gHth/gHtl [b][l][i] bf16 hi/lo
// grid (L/32, D/32, B), 256 threads
// ---------------------------------------------------------------------------
__global__ __launch_bounds__(256) void hsplit_kernel(const float* __restrict__ H)
{
    __shared__ float t[32][33];
    const int b = blockIdx.z;
    const int l0 = blockIdx.x * 32, i0 = blockIdx.y * 32;
    const int tx = threadIdx.x & 31, ty = threadIdx.x >> 5;

    const float* Hb = H + ((size_t)b * D + i0) * L + l0;
    #pragma unroll
    for (int r = 0; r < 4; r++)
        t[ty + 8 * r][tx] = Hb[(size_t)(ty + 8 * r) * L + tx];
    __syncthreads();

    #pragma unroll
    for (int r = 0; r < 4; r++) {
        float v = t[tx][ty + 8 * r];
        size_t idx = ((size_t)b * L + l0 + ty + 8 * r) * D + i0 + tx;
        __nv_bfloat16 h = __float2bfloat16(v);
        gHth[idx] = h;
        gHtl[idx] = __float2bfloat16(v - __bfloat162float(h));
    }
}

// ---------------------------------------------------------------------------
// W split: [Wk, Wq, Wv] fp32 -> gWh/gWl bf16 hi/lo
// ---------------------------------------------------------------------------
__global__ __launch_bounds__(256) void wsplit_kernel(
    const float* __restrict__ Wk, const float* __restrict__ Wq,
    const float* __restrict__ Wv)
{
    int idx = blockIdx.x * 256 + threadIdx.x;
    if (idx >= 3 * DD) return;
    int which = idx / DD, off = idx % DD;
    const float* W = (which == 0) ? Wk : (which == 1) ? Wq : Wv;
    float v = W[off];
    __nv_bfloat16 h = __float2bfloat16(v);
    gWh[idx] = h;
    gWl[idx] = __float2bfloat16(v - __bfloat162float(h));
}

// ---------------------------------------------------------------------------
// Row softmax over last dim (L=2048), in place + bf16 hi/lo split output.
// ---------------------------------------------------------------------------
__global__ __launch_bounds__(256) void softmax_kernel(float* __restrict__ A)
{
    __shared__ float red[256];
    const size_t base = (size_t)blockIdx.x * L;
    float* row = A + base;
    const int tid = threadIdx.x;

    float v[8];
    float m = -INFINITY;
    #pragma unroll
    for (int j = 0; j < 8; j++) {
        v[j] = row[tid + j * 256];
        m = fmaxf(m, v[j]);
    }
    red[tid] = m;
    __syncthreads();
    #pragma unroll
    for (int s = 128; s > 0; s >>= 1) {
        if (tid < s) red[tid] = fmaxf(red[tid], red[tid + s]);
        __syncthreads();
    }
    m = red[0];
    __syncthreads();

    float sum = 0.0f;
    #pragma unroll
    for (int j = 0; j < 8; j++) {
        v[j] = expf(v[j] - m);
        sum += v[j];
    }
    red[tid] = sum;
    __syncthreads();
    #pragma unroll
    for (int s = 128; s > 0; s >>= 1) {
        if (tid < s) red[tid] += red[tid + s];
        __syncthreads();
    }
    float inv = 1.0f / red[0];
    #pragma unroll
    for (int j = 0; j < 8; j++) {
        int idx = tid + j * 256;
        float a = v[j] * inv;
        row[idx] = a;
        __nv_bfloat16 h = __float2bfloat16(a);
        gAh[base + idx] = h;
        gAl[base + idx] = __float2bfloat16(a - __bfloat162float(h));
    }
}

// ---------------------------------------------------------------------------
extern "C" void kernel_launch(void* const* d_in, const int* in_sizes, int n_in,
                              void* d_out, int out_size)
{
    const float* H  = (const float*)d_in[0];
    const float* Wk = (const float*)d_in[1];
    const float* bk = (const float*)d_in[2];
    const float* Wq = (const float*)d_in[3];
    const float* bq = (const float*)d_in[4];
    const float* Wv = (const float*)d_in[5];
    const float* bv = (const float*)d_in[6];

    float* C_out = (float*)d_out;                    // [B, L, D]
    float* A_out = C_out + (size_t)B * L * D;        // [B, L, L]

    cudaFuncSetAttribute(mm3_kernel<0>, cudaFuncAttributeMaxDynamicSharedMemorySize, MM3_SMEM);
    cudaFuncSetAttribute(mm3_kernel<1>, cudaFuncAttributeMaxDynamicSharedMemorySize, MM3_SMEM);
    cudaFuncSetAttribute(mm3_kernel<2>, cudaFuncAttributeMaxDynamicSharedMemorySize, MM3_SMEM);

    __nv_bfloat16 *qh, *ql, *kh, *kl, *vh, *vl, *ah, *al, *hth, *htl, *wh, *wl;
    cudaGetSymbolAddress((void**)&qh, gQh);   cudaGetSymbolAddress((void**)&ql, gQl);
    cudaGetSymbolAddress((void**)&kh, gKh);   cudaGetSymbolAddress((void**)&kl, gKl);
    cudaGetSymbolAddress((void**)&vh, gVth);  cudaGetSymbolAddress((void**)&vl, gVtl);
    cudaGetSymbolAddress((void**)&ah, gAh);   cudaGetSymbolAddress((void**)&al, gAl);
    cudaGetSymbolAddress((void**)&hth, gHth); cudaGetSymbolAddress((void**)&htl, gHtl);
    cudaGetSymbolAddress((void**)&wh, gWh);   cudaGetSymbolAddress((void**)&wl, gWl);

    // 0) splits
    wsplit_kernel<<<(3 * DD + 255) / 256, 256>>>(Wk, Wq, Wv);
    {
        dim3 grid(L / 32, D / 32, B);
        hsplit_kernel<<<grid, 256>>>(H);
    }

    // 1) Q = elu(Ht Wq^T + bq): A=Ht rows l, B=Wq rows o -> [l][o]
    {
        dim3 grid(L / 128, D / 128, B);
        mm3_kernel<1><<<grid, 256, MM3_SMEM>>>(
            hth, htl, (size_t)L * D, D,
            wh + 1 * DD, wl + 1 * DD, 0, D,
            nullptr, qh, ql, bq, (size_t)L * D, D,
            D / 32, 1.0f);
        mm3_kernel<1><<<grid, 256, MM3_SMEM>>>(
            hth, htl, (size_t)L * D, D,
            wh + 0 * DD, wl + 0 * DD, 0, D,
            nullptr, kh, kl, bk, (size_t)L * D, D,
            D / 32, 1.0f);
    }
    // V^T = elu(Wv Ht^T + bv[row]): A=Wv rows o, B=Ht rows l -> [o][l]
    {
        dim3 grid(D / 128, L / 128, B);
        mm3_kernel<2><<<grid, 256, MM3_SMEM>>>(
            wh + 2 * DD, wl + 2 * DD, 0, D,
            hth, htl, (size_t)L * D, D,
            nullptr, vh, vl, bv, (size_t)D * L, L,
            D / 32, 1.0f);
    }

    // 2) E = scale * Q K^T
    {
        dim3 grid(L / 128, L / 128, B);
        mm3_kernel<0><<<grid, 256, MM3_SMEM>>>(
            qh, ql, (size_t)L * D, D,
            kh, kl, (size_t)L * D, D,
            A_out, nullptr, nullptr, nullptr, (size_t)L * L, L,
            D / 32, 0.044194173824159216f);
    }

    // 3) softmax rows + split bf16 A
    softmax_kernel<<<B * L, 256>>>(A_out);

    // 4) C = A V
    {
        dim3 grid(L / 128, D / 128, B);
        mm3_kernel<0><<<grid, 256, MM3_SMEM>>>(
            ah, al, (size_t)L * L, L,
            vh, vl, (size_t)D * L, L,
            C_out, nullptr, nullptr, nullptr, (size_t)L * D, D,
            L / 32, 1.0f);
    }
}

// round 6
// speedup vs baseline: 2.1108x; 1.0139x over previous
#include <cuda_runtime.h>
#include <cuda_bf16.h>
#include <math.h>
#include <stdint.h>

#define B 8
#define D 512
#define L 2048
#define DD (512*512)

#define BLD (8u*2048u*512u)            // 8388608
#define BLL (8ull*2048ull*2048ull)     // 33554432

// bf16 hi/lo split operands
__device__ __align__(128) __nv_bfloat16 gQh[BLD], gQl[BLD];
__device__ __align__(128) __nv_bfloat16 gKh[BLD], gKl[BLD];
__device__ __align__(128) __nv_bfloat16 gVth[BLD], gVtl[BLD];   // V^T: [b][d][l]
__device__ __align__(128) __nv_bfloat16 gAh[BLL], gAl[BLL];
__device__ __align__(128) __nv_bfloat16 gHth[BLD], gHtl[BLD];   // H^T: [b][l][i]
__device__ __align__(128) __nv_bfloat16 gWh[3*DD], gWl[3*DD];   // [Wk,Wq,Wv][o][i]

// ---------------------------------------------------------------------------
__device__ __forceinline__ uint32_t smem_u32(const void* p) {
    uint32_t a;
    asm("{ .reg .u64 t; cvta.to.shared.u64 t, %1; cvt.u32.u64 %0, t; }"
        : "=r"(a) : "l"(p));
    return a;
}

__device__ __forceinline__ void ldsm_x4(uint32_t* r, uint32_t addr) {
    asm volatile("ldmatrix.sync.aligned.m8n8.x4.shared.b16 {%0,%1,%2,%3}, [%4];"
        : "=r"(r[0]), "=r"(r[1]), "=r"(r[2]), "=r"(r[3]) : "r"(addr));
}

__device__ __forceinline__ void mma_bf16(float* c, const uint32_t* a, const uint32_t* b) {
    asm volatile(
        "mma.sync.aligned.m16n8k16.row.col.f32.bf16.bf16.f32 "
        "{%0,%1,%2,%3}, {%4,%5,%6,%7}, {%8,%9}, {%0,%1,%2,%3};"
        : "+f"(c[0]), "+f"(c[1]), "+f"(c[2]), "+f"(c[3])
        : "r"(a[0]), "r"(a[1]), "r"(a[2]), "r"(a[3]), "r"(b[0]), "r"(b[1]));
}

__device__ __forceinline__ void cp16(uint32_t saddr, const void* gaddr) {
    asm volatile("cp.async.cg.shared.global [%0], [%1], 16;"
        :: "r"(saddr), "l"(gaddr) : "memory");
}
#define CP_COMMIT() asm volatile("cp.async.commit_group;" ::: "memory")
#define CP_WAIT0()  asm volatile("cp.async.wait_group 0;" ::: "memory")

__device__ __forceinline__ float elu_f(float x) {
    return x > 0.0f ? x : expm1f(x);
}

__device__ __forceinline__ void split_store2(float f0, float f1,
                                             __nv_bfloat16* hi, __nv_bfloat16* lo)
{
    __nv_bfloat162 h, l;
    h.x = __float2bfloat16(f0);
    h.y = __float2bfloat16(f1);
    l.x = __float2bfloat16(f0 - __bfloat162float(h.x));
    l.y = __float2bfloat16(f1 - __bfloat162float(h.y));
    *(__nv_bfloat162*)hi = h;
    *(__nv_bfloat162*)lo = l;
}

// ---------------------------------------------------------------------------
// 3-way split GEMM: acc[m,n] = sum_k (Ah+Al)[m,k]*(Bh+Bl)[n,k]  (hh+hl+lh)
// CTA tile 128x128, K-chunk 32. 8 warps = (wm 0..3)x(wn 0..1), 32x64 each.
// 2 CTAs/SM. Single __syncthreads per chunk (issue-after-barrier pipeline).
// EPI 0: Cout = scale*acc (fp32)
// EPI 1: split(elu(acc + bias[col])) -> Oh/Ol
// EPI 2: split(elu(acc + bias[row])) -> Oh/Ol
// ---------------------------------------------------------------------------
#define ROWB  80
#define TILEB (128 * ROWB)          // 10240
#define STAGEB (4 * TILEB)          // 40960
#define MM3_SMEM (2 * STAGEB)       // 81920

template<int EPI>
__global__ __launch_bounds__(256, 2) void mm3_kernel(
    const __nv_bfloat16* __restrict__ Ah, const __nv_bfloat16* __restrict__ Al,
    size_t sA, int ldA,
    const __nv_bfloat16* __restrict__ Bh, const __nv_bfloat16* __restrict__ Bl,
    size_t sB, int ldB,
    float* __restrict__ Cout,
    __nv_bfloat16* __restrict__ Oh, __nv_bfloat16* __restrict__ Ol,
    const float* __restrict__ bias,
    size_t sC, int ldC,
    int nchunks, float scale)
{
    extern __shared__ char smem[];
    const uint32_t sbase = smem_u32(smem);
    const int tid = threadIdx.x, wid = tid >> 5, lane = tid & 31;
    const int wm = wid & 3, wn = wid >> 2;
    const int m0 = blockIdx.x * 128, n0 = blockIdx.y * 128, bz = blockIdx.z;

    const __nv_bfloat16* srcA_h = Ah + (size_t)bz * sA + (size_t)m0 * ldA;
    const __nv_bfloat16* srcA_l = Al + (size_t)bz * sA + (size_t)m0 * ldA;
    const __nv_bfloat16* srcB_h = Bh + (size_t)bz * sB + (size_t)n0 * ldB;
    const __nv_bfloat16* srcB_l = Bl + (size_t)bz * sB + (size_t)n0 * ldB;

    const int r0i = (tid * 2) >> 2,      s0i = (tid * 2) & 3;
    const int r1i = (tid * 2 + 1) >> 2,  s1i = (tid * 2 + 1) & 3;

#define ISSUE_CHUNK(ch) do { \
        const int _k0 = (ch) * 32; \
        const uint32_t _sb = sbase + ((ch) & 1) * STAGEB; \
        cp16(_sb + 0*TILEB + r0i*ROWB + s0i*16, srcA_h + (size_t)r0i*ldA + _k0 + s0i*8); \
        cp16(_sb + 0*TILEB + r1i*ROWB + s1i*16, srcA_h + (size_t)r1i*ldA + _k0 + s1i*8); \
        cp16(_sb + 1*TILEB + r0i*ROWB + s0i*16, srcA_l + (size_t)r0i*ldA + _k0 + s0i*8); \
        cp16(_sb + 1*TILEB + r1i*ROWB + s1i*16, srcA_l + (size_t)r1i*ldA + _k0 + s1i*8); \
        cp16(_sb + 2*TILEB + r0i*ROWB + s0i*16, srcB_h + (size_t)r0i*ldB + _k0 + s0i*8); \
        cp16(_sb + 2*TILEB + r1i*ROWB + s1i*16, srcB_h + (size_t)r1i*ldB + _k0 + s1i*8); \
        cp16(_sb + 3*TILEB + r0i*ROWB + s0i*16, srcB_l + (size_t)r0i*ldB + _k0 + s0i*8); \
        cp16(_sb + 3*TILEB + r1i*ROWB + s1i*16, srcB_l + (size_t)r1i*ldB + _k0 + s1i*8); \
        CP_COMMIT(); \
    } while (0)

    float acc[2][8][4];
    #pragma unroll
    for (int i = 0; i < 2; i++)
        #pragma unroll
        for (int j = 0; j < 8; j++)
            #pragma unroll
            for (int t = 0; t < 4; t++) acc[i][j][t] = 0.0f;

    const int rowA_l = lane & 15;
    const uint32_t offA_l = (uint32_t)rowA_l * ROWB + (lane >> 4) * 16;
    const int rowB_l = (lane & 7) + ((lane & 16) ? 8 : 0);
    const uint32_t offB_l = (uint32_t)rowB_l * ROWB + ((lane & 8) ? 16 : 0);

    ISSUE_CHUNK(0);

    for (int ch = 0; ch < nchunks; ch++) {
        // All outstanding copies (only chunk ch's group at this point) complete.
        CP_WAIT0();
        // Barrier also guarantees every warp finished compute(ch-1), so the
        // buffer (ch+1)&1 == (ch-1)&1 is free to refill after it.
        __syncthreads();
        if (ch + 1 < nchunks) ISSUE_CHUNK(ch + 1);

        const uint32_t sb = sbase + (ch & 1) * STAGEB;
        #pragma unroll
        for (int ks = 0; ks < 2; ks++) {
            const uint32_t kb = ks * 32;
            uint32_t ah[2][4], al[2][4];
            #pragma unroll
            for (int i = 0; i < 2; i++) {
                uint32_t base = sb + (uint32_t)(wm * 32 + i * 16) * ROWB + kb;
                ldsm_x4(ah[i], base + 0*TILEB + offA_l);
                ldsm_x4(al[i], base + 1*TILEB + offA_l);
            }
            // Process B in 2 halves of 32 cols (keeps live regs <= 128)
            #pragma unroll
            for (int half = 0; half < 2; half++) {
                uint32_t bh[2][4], bl[2][4];
                #pragma unroll
                for (int j2 = 0; j2 < 2; j2++) {
                    uint32_t base = sb +
                        (uint32_t)(wn * 64 + (half * 2 + j2) * 16) * ROWB + kb;
                    ldsm_x4(bh[j2], base + 2*TILEB + offB_l);
                    ldsm_x4(bl[j2], base + 3*TILEB + offB_l);
                }
                // 3 passes (hh, hl, lh): 8 independent MMAs between acc reuses
                #pragma unroll
                for (int p = 0; p < 3; p++) {
                    #pragma unroll
                    for (int i = 0; i < 2; i++)
                        #pragma unroll
                        for (int j = 0; j < 4; j++) {
                            const uint32_t* ap = (p == 2) ? al[i] : ah[i];
                            const uint32_t* bp = (p == 1)
                                ? &bl[j >> 1][(j & 1) * 2]
                                : &bh[j >> 1][(j & 1) * 2];
                            mma_bf16(acc[i][half * 4 + j], ap, bp);
                        }
                }
            }
        }
    }
#undef ISSUE_CHUNK

    // epilogue
    const int g = lane >> 2, tg = lane & 3;
    #pragma unroll
    for (int i = 0; i < 2; i++) {
        const int r0 = m0 + wm * 32 + i * 16 + g;
        #pragma unroll
        for (int j = 0; j < 8; j++) {
            const int c = n0 + wn * 64 + j * 8 + tg * 2;
            if (EPI == 0) {
                float* dst = Cout + (size_t)bz * sC;
                float2 v0 = make_float2(acc[i][j][0] * scale, acc[i][j][1] * scale);
                float2 v1 = make_float2(acc[i][j][2] * scale, acc[i][j][3] * scale);
                *(float2*)(dst + (size_t)r0 * ldC + c) = v0;
                *(float2*)(dst + (size_t)(r0 + 8) * ldC + c) = v1;
            } else {
                __nv_bfloat16* oh = Oh + (size_t)bz * sC;
                __nv_bfloat16* ol = Ol + (size_t)bz * sC;
                float f00, f01, f10, f11;
                if (EPI == 1) {
                    float b0 = bias[c], b1 = bias[c + 1];
                    f00 = elu_f(acc[i][j][0] + b0);
                    f01 = elu_f(acc[i][j][1] + b1);
                    f10 = elu_f(acc[i][j][2] + b0);
                    f11 = elu_f(acc[i][j][3] + b1);
                } else {
                    float b0 = bias[r0], b1 = bias[r0 + 8];
                    f00 = elu_f(acc[i][j][0] + b0);
                    f01 = elu_f(acc[i][j][1] + b0);
                    f10 = elu_f(acc[i][j][2] + b1);
                    f11 = elu_f(acc[i][j][3] + b1);
                }
                split_store2(f00, f01, oh + (size_t)r0 * ldC + c,
                                       ol + (size_t)r0 * ldC + c);
                split_store2(f10, f11, oh + (size_t)(r0 + 8) * ldC + c,
                                       ol + (size_t)(r0 + 8) * ldC + c);
            }
        }
    }
}

// ---------------------------------------------------------------------------
// H^T split: H[b][i][l] fp32 -> gHth/gHtl [b][l][i] bf16 hi/lo
// ---------------------------------------------------------------------------
__global__ __launch_bounds__(256) void hsplit_kernel(const float* __restrict__ H)
{
    __shared__ float t[32][33];
    const int b = blockIdx.z;
    const int l0 = blockIdx.x * 32, i0 = blockIdx.y * 32;
    const int tx = threadIdx.x & 31, ty = threadIdx.x >> 5;

    const float* Hb = H + ((size_t)b * D + i0) * L + l0;
    #pragma unroll
    for (int r = 0; r < 4; r++)
        t[ty + 8 * r][tx] = Hb[(size_t)(ty + 8 * r) * L + tx];
    __syncthreads();

    #pragma unroll
    for (int r = 0; r < 4; r++) {
        float v = t[tx][ty + 8 * r];
        size_t idx = ((size_t)b * L + l0 + ty + 8 * r) * D + i0 + tx;
        __nv_bfloat16 h = __float2bfloat16(v);
        gHth[idx] = h;
        gHtl[idx] = __float2bfloat16(v - __bfloat162float(h));
    }
}

// ---------------------------------------------------------------------------
// W split: [Wk, Wq, Wv] fp32 -> gWh/gWl bf16 hi/lo
// ---------------------------------------------------------------------------
__global__ __launch_bounds__(256) void wsplit_kernel(
    const float* __restrict__ Wk, const float* __restrict__ Wq,
    const float* __restrict__ Wv)
{
    int idx = blockIdx.x * 256 + threadIdx.x;
    if (idx >= 3 * DD) return;
    int which = idx / DD, off = idx % DD;
    const float* W = (which == 0) ? Wk : (which == 1) ? Wq : Wv;
    float v = W[off];
    __nv_bfloat16 h = __float2bfloat16(v);
    gWh[idx] = h;
    gWl[idx] = __float2bfloat16(v - __bfloat162float(h));
}

// ---------------------------------------------------------------------------
// Row softmax (L=2048), warp-shuffle reductions, float4 I/O, __expf.
// In place fp32 + bf16 hi/lo split output.
// ---------------------------------------------------------------------------
__global__ __launch_bounds__(256) void softmax_kernel(float* __restrict__ A)
{
    __shared__ float red[8];
    const size_t base = (size_t)blockIdx.x * L;
    float4* rowv = (float4*)(A + base);
    const int tid = threadIdx.x, lane = tid & 31, wid = tid >> 5;

    float4 v[2];
    v[0] = rowv[tid];
    v[1] = rowv[tid + 256];

    float m = fmaxf(fmaxf(fmaxf(v[0].x, v[0].y), fmaxf(v[0].z, v[0].w)),
                    fmaxf(fmaxf(v[1].x, v[1].y), fmaxf(v[1].z, v[1].w)));
    #pragma unroll
    for (int s = 16; s > 0; s >>= 1)
        m = fmaxf(m, __shfl_xor_sync(0xFFFFFFFFu, m, s));
    if (lane == 0) red[wid] = m;
    __syncthreads();
    {
        float t = red[lane & 7];
        #pragma unroll
        for (int s = 4; s > 0; s >>= 1)
            t = fmaxf(t, __shfl_xor_sync(0xFFFFFFFFu, t, s));
        m = t;
    }

    float sum = 0.0f;
    #pragma unroll
    for (int q = 0; q < 2; q++) {
        v[q].x = __expf(v[q].x - m);
        v[q].y = __expf(v[q].y - m);
        v[q].z = __expf(v[q].z - m);
        v[q].w = __expf(v[q].w - m);
        sum += (v[q].x + v[q].y) + (v[q].z + v[q].w);
    }
    #pragma unroll
    for (int s = 16; s > 0; s >>= 1)
        sum += __shfl_xor_sync(0xFFFFFFFFu, sum, s);
    __syncthreads();
    if (lane == 0) red[wid] = sum;
    __syncthreads();
    {
        float t = red[lane & 7];
        #pragma unroll
        for (int s = 4; s > 0; s >>= 1)
            t += __shfl_xor_sync(0xFFFFFFFFu, t, s);
        sum = t;
    }
    const float inv = 1.0f / sum;

    __nv_bfloat162* ahp = (__nv_bfloat162*)(gAh + base);
    __nv_bfloat162* alp = (__nv_bfloat162*)(gAl + base);
    #pragma unroll
    for (int q = 0; q < 2; q++) {
        float4 a;
        a.x = v[q].x * inv; a.y = v[q].y * inv;
        a.z = v[q].z * inv; a.w = v[q].w * inv;
        rowv[tid + q * 256] = a;

        __nv_bfloat162 h0, h1, l0, l1;
        h0.x = __float2bfloat16(a.x); h0.y = __float2bfloat16(a.y);
        h1.x = __float2bfloat16(a.z); h1.y = __float2bfloat16(a.w);
        l0.x = __float2bfloat16(a.x - __bfloat162float(h0.x));
        l0.y = __float2bfloat16(a.y - __bfloat162float(h0.y));
        l1.x = __float2bfloat16(a.z - __bfloat162float(h1.x));
        l1.y = __float2bfloat16(a.w - __bfloat162float(h1.y));
        ahp[(tid + q * 256) * 2]     = h0;
        ahp[(tid + q * 256) * 2 + 1] = h1;
        alp[(tid + q * 256) * 2]     = l0;
        alp[(tid + q * 256) * 2 + 1] = l1;
    }
}

// ---------------------------------------------------------------------------
extern "C" void kernel_launch(void* const* d_in, const int* in_sizes, int n_in,
                              void* d_out, int out_size)
{
    const float* H  = (const float*)d_in[0];
    const float* Wk = (const float*)d_in[1];
    const float* bk = (const float*)d_in[2];
    const float* Wq = (const float*)d_in[3];
    const float* bq = (const float*)d_in[4];
    const float* Wv = (const float*)d_in[5];
    const float* bv = (const float*)d_in[6];

    float* C_out = (float*)d_out;                    // [B, L, D]
    float* A_out = C_out + (size_t)B * L * D;        // [B, L, L]

    cudaFuncSetAttribute(mm3_kernel<0>, cudaFuncAttributeMaxDynamicSharedMemorySize, MM3_SMEM);
    cudaFuncSetAttribute(mm3_kernel<1>, cudaFuncAttributeMaxDynamicSharedMemorySize, MM3_SMEM);
    cudaFuncSetAttribute(mm3_kernel<2>, cudaFuncAttributeMaxDynamicSharedMemorySize, MM3_SMEM);

    __nv_bfloat16 *qh, *ql, *kh, *kl, *vh, *vl, *ah, *al, *hth, *htl, *wh, *wl;
    cudaGetSymbolAddress((void**)&qh, gQh);   cudaGetSymbolAddress((void**)&ql, gQl);
    cudaGetSymbolAddress((void**)&kh, gKh);   cudaGetSymbolAddress((void**)&kl, gKl);
    cudaGetSymbolAddress((void**)&vh, gVth);  cudaGetSymbolAddress((void**)&vl, gVtl);
    cudaGetSymbolAddress((void**)&ah, gAh);   cudaGetSymbolAddress((void**)&al, gAl);
    cudaGetSymbolAddress((void**)&hth, gHth); cudaGetSymbolAddress((void**)&htl, gHtl);
    cudaGetSymbolAddress((void**)&wh, gWh);   cudaGetSymbolAddress((void**)&wl, gWl);

    // 0) splits
    wsplit_kernel<<<(3 * DD + 255) / 256, 256>>>(Wk, Wq, Wv);
    {
        dim3 grid(L / 32, D / 32, B);
        hsplit_kernel<<<grid, 256>>>(H);
    }

    // 1) Q = elu(Ht Wq^T + bq): A=Ht rows l, B=Wq rows o -> [l][o]
    {
        dim3 grid(L / 128, D / 128, B);
        mm3_kernel<1><<<grid, 256, MM3_SMEM>>>(
            hth, htl, (size_t)L * D, D,
            wh + 1 * DD, wl + 1 * DD, 0, D,
            nullptr, qh, ql, bq, (size_t)L * D, D,
            D / 32, 1.0f);
        mm3_kernel<1><<<grid, 256, MM3_SMEM>>>(
            hth, htl, (size_t)L * D, D,
            wh + 0 * DD, wl + 0 * DD, 0, D,
            nullptr, kh, kl, bk, (size_t)L * D, D,
            D / 32, 1.0f);
    }
    // V^T = elu(Wv Ht^T + bv[row]): A=Wv rows o, B=Ht rows l -> [o][l]
    {
        dim3 grid(D / 128, L / 128, B);
        mm3_kernel<2><<<grid, 256, MM3_SMEM>>>(
            wh + 2 * DD, wl + 2 * DD, 0, D,
            hth, htl, (size_t)L * D, D,
            nullptr, vh, vl, bv, (size_t)D * L, L,
            D / 32, 1.0f);
    }

    // 2) E = scale * Q K^T
    {
        dim3 grid(L / 128, L / 128, B);
        mm3_kernel<0><<<grid, 256, MM3_SMEM>>>(
            qh, ql, (size_t)L * D, D,
            kh, kl, (size_t)L * D, D,
            A_out, nullptr, nullptr, nullptr, (size_t)L * L, L,
            D / 32, 0.044194173824159216f);
    }

    // 3) softmax rows + split bf16 A
    softmax_kernel<<<B * L, 256>>>(A_out);

    // 4) C = A V
    {
        dim3 grid(L / 128, D / 128, B);
        mm3_kernel<0><<<grid, 256, MM3_SMEM>>>(
            ah, al, (size_t)L * L, L,
            vh, vl, (size_t)D * L, L,
            C_out, nullptr, nullptr, nullptr, (size_t)L * D, D,
            L / 32, 1.0f);
    }
}

// round 7
// speedup vs baseline: 2.8436x; 1.3472x over previous
#include <cuda_runtime.h>
#include <cuda_fp16.h>
#include <math.h>
#include <stdint.h>

#define B 8
#define D 512
#define L 2048
#define DD (512*512)

#define BLD (8u*2048u*512u)            // 8388608
#define BLL (8ull*2048ull*2048ull)     // 33554432

// fp16 operands: A-side operands split hi/lo, B-side single
__device__ __align__(128) __half gQh[BLD], gQl[BLD];
__device__ __align__(128) __half gKh[BLD];                 // single
__device__ __align__(128) __half gVth[BLD];                // V^T single: [b][d][l]
__device__ __align__(128) __half gAh[BLL], gAl[BLL];
__device__ __align__(128) __half gHth[BLD], gHtl[BLD];     // H^T: [b][l][i]
__device__ __align__(128) __half gWh[3*DD], gWl[3*DD];     // [Wk,Wq,Wv][o][i]

// ---------------------------------------------------------------------------
__device__ __forceinline__ uint32_t smem_u32(const void* p) {
    uint32_t a;
    asm("{ .reg .u64 t; cvta.to.shared.u64 t, %1; cvt.u32.u64 %0, t; }"
        : "=r"(a) : "l"(p));
    return a;
}

__device__ __forceinline__ void ldsm_x4(uint32_t* r, uint32_t addr) {
    asm volatile("ldmatrix.sync.aligned.m8n8.x4.shared.b16 {%0,%1,%2,%3}, [%4];"
        : "=r"(r[0]), "=r"(r[1]), "=r"(r[2]), "=r"(r[3]) : "r"(addr));
}

__device__ __forceinline__ void mma_fp16(float* c, const uint32_t* a, const uint32_t* b) {
    asm volatile(
        "mma.sync.aligned.m16n8k16.row.col.f32.f16.f16.f32 "
        "{%0,%1,%2,%3}, {%4,%5,%6,%7}, {%8,%9}, {%0,%1,%2,%3};"
        : "+f"(c[0]), "+f"(c[1]), "+f"(c[2]), "+f"(c[3])
        : "r"(a[0]), "r"(a[1]), "r"(a[2]), "r"(a[3]), "r"(b[0]), "r"(b[1]));
}

__device__ __forceinline__ void cp16(uint32_t saddr, const void* gaddr) {
    asm volatile("cp.async.cg.shared.global [%0], [%1], 16;"
        :: "r"(saddr), "l"(gaddr) : "memory");
}
#define CP_COMMIT() asm volatile("cp.async.commit_group;" ::: "memory")
#define CP_WAIT0()  asm volatile("cp.async.wait_group 0;" ::: "memory")

__device__ __forceinline__ float elu_f(float x) {
    return x > 0.0f ? x : expm1f(x);
}

// ---------------------------------------------------------------------------
// 2-pass split GEMM: acc[m,n] = sum_k (Ah+Al)[m,k] * Bh[n,k]
// (A split fp16 hi/lo — exact; B single fp16 — only error source, 2^-12.)
// CTA tile 128x128, K-chunk 32. 8 warps = (wm 0..3)x(wn 0..1), 32x64 each.
// 2 CTAs/SM; single __syncthreads per chunk.
// EPI 0: Cout = scale*acc (fp32)
// EPI 1: split hi/lo fp16 of elu(acc + bias[col])
// EPI 2: single fp16 of elu(acc + bias[row])
// EPI 3: single fp16 of elu(acc + bias[col])
// ---------------------------------------------------------------------------
#define ROWB  80
#define TILEB (128 * ROWB)          // 10240
#define STAGEB (3 * TILEB)          // 30720
#define MM2_SMEM (2 * STAGEB)       // 61440

template<int EPI>
__global__ __launch_bounds__(256, 2) void mm2_kernel(
    const __half* __restrict__ Ah, const __half* __restrict__ Al,
    size_t sA, int ldA,
    const __half* __restrict__ Bh,
    size_t sB, int ldB,
    float* __restrict__ Cout,
    __half* __restrict__ Oh, __half* __restrict__ Ol,
    const float* __restrict__ bias,
    size_t sC, int ldC,
    int nchunks, float scale)
{
    extern __shared__ char smem[];
    const uint32_t sbase = smem_u32(smem);
    const int tid = threadIdx.x, wid = tid >> 5, lane = tid & 31;
    const int wm = wid & 3, wn = wid >> 2;
    const int m0 = blockIdx.x * 128, n0 = blockIdx.y * 128, bz = blockIdx.z;

    const __half* srcA_h = Ah + (size_t)bz * sA + (size_t)m0 * ldA;
    const __half* srcA_l = Al + (size_t)bz * sA + (size_t)m0 * ldA;
    const __half* srcB_h = Bh + (size_t)bz * sB + (size_t)n0 * ldB;

    const int r0i = (tid * 2) >> 2,      s0i = (tid * 2) & 3;
    const int r1i = (tid * 2 + 1) >> 2,  s1i = (tid * 2 + 1) & 3;

#define ISSUE_CHUNK(ch) do { \
        const int _k0 = (ch) * 32; \
        const uint32_t _sb = sbase + ((ch) & 1) * STAGEB; \
        cp16(_sb + 0*TILEB + r0i*ROWB + s0i*16, srcA_h + (size_t)r0i*ldA + _k0 + s0i*8); \
        cp16(_sb + 0*TILEB + r1i*ROWB + s1i*16, srcA_h + (size_t)r1i*ldA + _k0 + s1i*8); \
        cp16(_sb + 1*TILEB + r0i*ROWB + s0i*16, srcA_l + (size_t)r0i*ldA + _k0 + s0i*8); \
        cp16(_sb + 1*TILEB + r1i*ROWB + s1i*16, srcA_l + (size_t)r1i*ldA + _k0 + s1i*8); \
        cp16(_sb + 2*TILEB + r0i*ROWB + s0i*16, srcB_h + (size_t)r0i*ldB + _k0 + s0i*8); \
        cp16(_sb + 2*TILEB + r1i*ROWB + s1i*16, srcB_h + (size_t)r1i*ldB + _k0 + s1i*8); \
        CP_COMMIT(); \
    } while (0)

    float acc[2][8][4];
    #pragma unroll
    for (int i = 0; i < 2; i++)
        #pragma unroll
        for (int j = 0; j < 8; j++)
            #pragma unroll
            for (int t = 0; t < 4; t++) acc[i][j][t] = 0.0f;

    const int rowA_l = lane & 15;
    const uint32_t offA_l = (uint32_t)rowA_l * ROWB + (lane >> 4) * 16;
    const int rowB_l = (lane & 7) + ((lane & 16) ? 8 : 0);
    const uint32_t offB_l = (uint32_t)rowB_l * ROWB + ((lane & 8) ? 16 : 0);

    ISSUE_CHUNK(0);

    for (int ch = 0; ch < nchunks; ch++) {
        CP_WAIT0();
        __syncthreads();
        if (ch + 1 < nchunks) ISSUE_CHUNK(ch + 1);

        const uint32_t sb = sbase + (ch & 1) * STAGEB;
        #pragma unroll
        for (int ks = 0; ks < 2; ks++) {
            const uint32_t kb = ks * 32;
            uint32_t ah[2][4], al[2][4];
            #pragma unroll
            for (int i = 0; i < 2; i++) {
                uint32_t base = sb + (uint32_t)(wm * 32 + i * 16) * ROWB + kb;
                ldsm_x4(ah[i], base + 0*TILEB + offA_l);
                ldsm_x4(al[i], base + 1*TILEB + offA_l);
            }
            #pragma unroll
            for (int half = 0; half < 2; half++) {
                uint32_t bh[2][4];
                #pragma unroll
                for (int j2 = 0; j2 < 2; j2++) {
                    uint32_t base = sb +
                        (uint32_t)(wn * 64 + (half * 2 + j2) * 16) * ROWB + kb;
                    ldsm_x4(bh[j2], base + 2*TILEB + offB_l);
                }
                // 2 passes (Ah, Al): 8 independent MMAs between acc reuses
                #pragma unroll
                for (int p = 0; p < 2; p++) {
                    #pragma unroll
                    for (int i = 0; i < 2; i++)
                        #pragma unroll
                        for (int j = 0; j < 4; j++) {
                            const uint32_t* ap = p ? al[i] : ah[i];
                            mma_fp16(acc[i][half * 4 + j], ap,
                                     &bh[j >> 1][(j & 1) * 2]);
                        }
                }
            }
        }
    }
#undef ISSUE_CHUNK

    // epilogue
    const int g = lane >> 2, tg = lane & 3;
    #pragma unroll
    for (int i = 0; i < 2; i++) {
        const int r0 = m0 + wm * 32 + i * 16 + g;
        #pragma unroll
        for (int j = 0; j < 8; j++) {
            const int c = n0 + wn * 64 + j * 8 + tg * 2;
            if (EPI == 0) {
                float* dst = Cout + (size_t)bz * sC;
                float2 v0 = make_float2(acc[i][j][0] * scale, acc[i][j][1] * scale);
                float2 v1 = make_float2(acc[i][j][2] * scale, acc[i][j][3] * scale);
                *(float2*)(dst + (size_t)r0 * ldC + c) = v0;
                *(float2*)(dst + (size_t)(r0 + 8) * ldC + c) = v1;
            } else {
                __half* oh = Oh + (size_t)bz * sC;
                float f00, f01, f10, f11;
                if (EPI == 2) {
                    float b0 = bias[r0], b1 = bias[r0 + 8];
                    f00 = elu_f(acc[i][j][0] + b0);
                    f01 = elu_f(acc[i][j][1] + b0);
                    f10 = elu_f(acc[i][j][2] + b1);
                    f11 = elu_f(acc[i][j][3] + b1);
                } else {
                    float b0 = bias[c], b1 = bias[c + 1];
                    f00 = elu_f(acc[i][j][0] + b0);
                    f01 = elu_f(acc[i][j][1] + b1);
                    f10 = elu_f(acc[i][j][2] + b0);
                    f11 = elu_f(acc[i][j][3] + b1);
                }
                __half2 h0 = __floats2half2_rn(f00, f01);
                __half2 h1 = __floats2half2_rn(f10, f11);
                *(__half2*)(oh + (size_t)r0 * ldC + c) = h0;
                *(__half2*)(oh + (size_t)(r0 + 8) * ldC + c) = h1;
                if (EPI == 1) {
                    __half* ol = Ol + (size_t)bz * sC;
                    __half2 l0 = __floats2half2_rn(f00 - __half2float(h0.x),
                                                   f01 - __half2float(h0.y));
                    __half2 l1 = __floats2half2_rn(f10 - __half2float(h1.x),
                                                   f11 - __half2float(h1.y));
                    *(__half2*)(ol + (size_t)r0 * ldC + c) = l0;
                    *(__half2*)(ol + (size_t)(r0 + 8) * ldC + c) = l1;
                }
            }
        }
    }
}

// ---------------------------------------------------------------------------
// H^T split: H[b][i][l] fp32 -> gHth/gHtl [b][l][i] fp16 hi/lo
// ---------------------------------------------------------------------------
__global__ __launch_bounds__(256) void hsplit_kernel(const float* __restrict__ H)
{
    __shared__ float t[32][33];
    const int b = blockIdx.z;
    const int l0 = blockIdx.x * 32, i0 = blockIdx.y * 32;
    const int tx = threadIdx.x & 31, ty = threadIdx.x >> 5;

    const float* Hb = H + ((size_t)b * D + i0) * L + l0;
    #pragma unroll
    for (int r = 0; r < 4; r++)
        t[ty + 8 * r][tx] = Hb[(size_t)(ty + 8 * r) * L + tx];
    __syncthreads();

    #pragma unroll
    for (int r = 0; r < 4; r++) {
        float v = t[tx][ty + 8 * r];
        size_t idx = ((size_t)b * L + l0 + ty + 8 * r) * D + i0 + tx;
        __half h = __float2half_rn(v);
        gHth[idx] = h;
        gHtl[idx] = __float2half_rn(v - __half2float(h));
    }
}

// ---------------------------------------------------------------------------
// W split: [Wk, Wq, Wv] fp32 -> gWh/gWl fp16 hi/lo
// ---------------------------------------------------------------------------
__global__ __launch_bounds__(256) void wsplit_kernel(
    const float* __restrict__ Wk, const float* __restrict__ Wq,
    const float* __restrict__ Wv)
{
    int idx = blockIdx.x * 256 + threadIdx.x;
    if (idx >= 3 * DD) return;
    int which = idx / DD, off = idx % DD;
    const float* W = (which == 0) ? Wk : (which == 1) ? Wq : Wv;
    float v = W[off];
    __half h = __float2half_rn(v);
    gWh[idx] = h;
    gWl[idx] = __float2half_rn(v - __half2float(h));
}

// ---------------------------------------------------------------------------
// Row softmax (L=2048), warp-shuffle reductions, float4 I/O, __expf.
// In place fp32 + fp16 hi/lo split output.
// ---------------------------------------------------------------------------
__global__ __launch_bounds__(256) void softmax_kernel(float* __restrict__ A)
{
    __shared__ float red[8];
    const size_t base = (size_t)blockIdx.x * L;
    float4* rowv = (float4*)(A + base);
    const int tid = threadIdx.x, lane = tid & 31, wid = tid >> 5;

    float4 v[2];
    v[0] = rowv[tid];
    v[1] = rowv[tid + 256];

    float m = fmaxf(fmaxf(fmaxf(v[0].x, v[0].y), fmaxf(v[0].z, v[0].w)),
                    fmaxf(fmaxf(v[1].x, v[1].y), fmaxf(v[1].z, v[1].w)));
    #pragma unroll
    for (int s = 16; s > 0; s >>= 1)
        m = fmaxf(m, __shfl_xor_sync(0xFFFFFFFFu, m, s));
    if (lane == 0) red[wid] = m;
    __syncthreads();
    {
        float t = red[lane & 7];
        #pragma unroll
        for (int s = 4; s > 0; s >>= 1)
            t = fmaxf(t, __shfl_xor_sync(0xFFFFFFFFu, t, s));
        m = t;
    }

    float sum = 0.0f;
    #pragma unroll
    for (int q = 0; q < 2; q++) {
        v[q].x = __expf(v[q].x - m);
        v[q].y = __expf(v[q].y - m);
        v[q].z = __expf(v[q].z - m);
        v[q].w = __expf(v[q].w - m);
        sum += (v[q].x + v[q].y) + (v[q].z + v[q].w);
    }
    #pragma unroll
    for (int s = 16; s > 0; s >>= 1)
        sum += __shfl_xor_sync(0xFFFFFFFFu, sum, s);
    __syncthreads();
    if (lane == 0) red[wid] = sum;
    __syncthreads();
    {
        float t = red[lane & 7];
        #pragma unroll
        for (int s = 4; s > 0; s >>= 1)
            t += __shfl_xor_sync(0xFFFFFFFFu, t, s);
        sum = t;
    }
    const float inv = 1.0f / sum;

    __half2* ahp = (__half2*)(gAh + base);
    __half2* alp = (__half2*)(gAl + base);
    #pragma unroll
    for (int q = 0; q < 2; q++) {
        float4 a;
        a.x = v[q].x * inv; a.y = v[q].y * inv;
        a.z = v[q].z * inv; a.w = v[q].w * inv;
        rowv[tid + q * 256] = a;

        __half2 h0 = __floats2half2_rn(a.x, a.y);
        __half2 h1 = __floats2half2_rn(a.z, a.w);
        __half2 l0 = __floats2half2_rn(a.x - __half2float(h0.x),
                                       a.y - __half2float(h0.y));
        __half2 l1 = __floats2half2_rn(a.z - __half2float(h1.x),
                                       a.w - __half2float(h1.y));
        ahp[(tid + q * 256) * 2]     = h0;
        ahp[(tid + q * 256) * 2 + 1] = h1;
        alp[(tid + q * 256) * 2]     = l0;
        alp[(tid + q * 256) * 2 + 1] = l1;
    }
}

// ---------------------------------------------------------------------------
extern "C" void kernel_launch(void* const* d_in, const int* in_sizes, int n_in,
                              void* d_out, int out_size)
{
    const float* H  = (const float*)d_in[0];
    const float* Wk = (const float*)d_in[1];
    const float* bk = (const float*)d_in[2];
    const float* Wq = (const float*)d_in[3];
    const float* bq = (const float*)d_in[4];
    const float* Wv = (const float*)d_in[5];
    const float* bv = (const float*)d_in[6];

    float* C_out = (float*)d_out;                    // [B, L, D]
    float* A_out = C_out + (size_t)B * L * D;        // [B, L, L]

    cudaFuncSetAttribute(mm2_kernel<0>, cudaFuncAttributeMaxDynamicSharedMemorySize, MM2_SMEM);
    cudaFuncSetAttribute(mm2_kernel<1>, cudaFuncAttributeMaxDynamicSharedMemorySize, MM2_SMEM);
    cudaFuncSetAttribute(mm2_kernel<2>, cudaFuncAttributeMaxDynamicSharedMemorySize, MM2_SMEM);
    cudaFuncSetAttribute(mm2_kernel<3>, cudaFuncAttributeMaxDynamicSharedMemorySize, MM2_SMEM);

    __half *qh, *ql, *kh, *vth, *ah, *al, *hth, *htl, *wh, *wl;
    cudaGetSymbolAddress((void**)&qh, gQh);   cudaGetSymbolAddress((void**)&ql, gQl);
    cudaGetSymbolAddress((void**)&kh, gKh);
    cudaGetSymbolAddress((void**)&vth, gVth);
    cudaGetSymbolAddress((void**)&ah, gAh);   cudaGetSymbolAddress((void**)&al, gAl);
    cudaGetSymbolAddress((void**)&hth, gHth); cudaGetSymbolAddress((void**)&htl, gHtl);
    cudaGetSymbolAddress((void**)&wh, gWh);   cudaGetSymbolAddress((void**)&wl, gWl);

    // 0) splits
    wsplit_kernel<<<(3 * DD + 255) / 256, 256>>>(Wk, Wq, Wv);
    {
        dim3 grid(L / 32, D / 32, B);
        hsplit_kernel<<<grid, 256>>>(H);
    }

    // 1) Q = elu(Ht Wq^T + bq): A=Ht(split) rows l, B=Wq(h) rows o -> [l][o], split out
    {
        dim3 grid(L / 128, D / 128, B);
        mm2_kernel<1><<<grid, 256, MM2_SMEM>>>(
            hth, htl, (size_t)L * D, D,
            wh + 1 * DD, 0, D,
            nullptr, qh, ql, bq, (size_t)L * D, D,
            D / 32, 1.0f);
        // K: same, single fp16 out
        mm2_kernel<3><<<grid, 256, MM2_SMEM>>>(
            hth, htl, (size_t)L * D, D,
            wh + 0 * DD, 0, D,
            nullptr, kh, nullptr, bk, (size_t)L * D, D,
            D / 32, 1.0f);
    }
    // V^T = elu(Wv Ht^T + bv[row]): A=Wv(split) rows o, B=Ht(h) rows l -> [o][l], single out
    {
        dim3 grid(D / 128, L / 128, B);
        mm2_kernel<2><<<grid, 256, MM2_SMEM>>>(
            wh + 2 * DD, wl + 2 * DD, 0, D,
            hth, (size_t)L * D, D,
            nullptr, vth, nullptr, bv, (size_t)D * L, L,
            D / 32, 1.0f);
    }

    // 2) E = scale * Q K^T : A=Q(split), B=K(h)
    {
        dim3 grid(L / 128, L / 128, B);
        mm2_kernel<0><<<grid, 256, MM2_SMEM>>>(
            qh, ql, (size_t)L * D, D,
            kh, (size_t)L * D, D,
            A_out, nullptr, nullptr, nullptr, (size_t)L * L, L,
            D / 32, 0.044194173824159216f);
    }

    // 3) softmax rows + split fp16 A
    softmax_kernel<<<B * L, 256>>>(A_out);

    // 4) C = A V : A=A(split), B=V^T(h)
    {
        dim3 grid(L / 128, D / 128, B);
        mm2_kernel<0><<<grid, 256, MM2_SMEM>>>(
            ah, al, (size_t)L * L, L,
            vth, (size_t)D * L, L,
            C_out, nullptr, nullptr, nullptr, (size_t)L * D, D,
            L / 32, 1.0f);
    }
}

// round 8
// speedup vs baseline: 3.8974x; 1.3705x over previous
#include <cuda_runtime.h>
#include <cuda_fp16.h>
#include <math.h>
#include <stdint.h>

#define B 8
#define D 512
#define L 2048
#define DD (512*512)

#define BLD (8u*2048u*512u)            // 8388608
#define BLL (8ull*2048ull*2048ull)     // 33554432

// fp16 operands: A-side operands split hi/lo, B-side single
__device__ __align__(128) __half gQh[BLD], gQl[BLD];
__device__ __align__(128) __half gKh[BLD];                 // single
__device__ __align__(128) __half gVth[BLD];                // V^T single: [b][d][l]
__device__ __align__(128) __half gAh[BLL];                 // softmax hi only
__device__ __align__(128) __half gHth[BLD], gHtl[BLD];     // H^T: [b][l][i]
__device__ __align__(128) __half gWh[3*DD], gWl[3*DD];     // [Wk,Wq,Wv][o][i]

// ---------------------------------------------------------------------------
__device__ __forceinline__ uint32_t smem_u32(const void* p) {
    uint32_t a;
    asm("{ .reg .u64 t; cvta.to.shared.u64 t, %1; cvt.u32.u64 %0, t; }"
        : "=r"(a) : "l"(p));
    return a;
}

__device__ __forceinline__ void ldsm_x4(uint32_t* r, uint32_t addr) {
    asm volatile("ldmatrix.sync.aligned.m8n8.x4.shared.b16 {%0,%1,%2,%3}, [%4];"
        : "=r"(r[0]), "=r"(r[1]), "=r"(r[2]), "=r"(r[3]) : "r"(addr));
}

__device__ __forceinline__ void mma_fp16(float* c, const uint32_t* a, const uint32_t* b) {
    asm volatile(
        "mma.sync.aligned.m16n8k16.row.col.f32.f16.f16.f32 "
        "{%0,%1,%2,%3}, {%4,%5,%6,%7}, {%8,%9}, {%0,%1,%2,%3};"
        : "+f"(c[0]), "+f"(c[1]), "+f"(c[2]), "+f"(c[3])
        : "r"(a[0]), "r"(a[1]), "r"(a[2]), "r"(a[3]), "r"(b[0]), "r"(b[1]));
}

__device__ __forceinline__ void cp16(uint32_t saddr, const void* gaddr) {
    asm volatile("cp.async.cg.shared.global [%0], [%1], 16;"
        :: "r"(saddr), "l"(gaddr) : "memory");
}
#define CP_COMMIT() asm volatile("cp.async.commit_group;" ::: "memory")
#define CP_WAIT0()  asm volatile("cp.async.wait_group 0;" ::: "memory")

__device__ __forceinline__ float elu_f(float x) {
    return x > 0.0f ? x : expm1f(x);
}

// ---------------------------------------------------------------------------
// Split GEMM: acc[m,n] = sum_k (Ah[+Al])[m,k] * Bh[n,k]
// NPASS=2: A split fp16 hi/lo (exact A); NPASS=1: A single fp16.
// CTA tile 128x128, K-chunk 64. 8 warps = (wm 0..3)x(wn 0..1), 32x64 each.
// 2 CTAs/SM; single __syncthreads per chunk.
// Tiles per stage: [Ah][Bh][Al?]  (Al only for NPASS=2)
// EPI 0: Cout = scale*acc (fp32)
// EPI 1: split hi/lo fp16 of elu(acc + bias[col])
// EPI 2: single fp16 of elu(acc + bias[row])
// EPI 3: single fp16 of elu(acc + bias[col])
// ---------------------------------------------------------------------------
#define ROWB  144                    // 64 halves (128B) + 16B pad
#define TILEB (128 * ROWB)           // 18432
#define SMEM_OF(npass) (2 * ((npass) + 1) * TILEB)

template<int EPI, int NPASS>
__global__ __launch_bounds__(256, 2) void mm2_kernel(
    const __half* __restrict__ Ah, const __half* __restrict__ Al,
    size_t sA, int ldA,
    const __half* __restrict__ Bh,
    size_t sB, int ldB,
    float* __restrict__ Cout,
    __half* __restrict__ Oh, __half* __restrict__ Ol,
    const float* __restrict__ bias,
    size_t sC, int ldC,
    int nchunks, float scale)
{
    constexpr int NT = NPASS + 1;          // tiles per stage
    constexpr int STAGEB = NT * TILEB;
    extern __shared__ char smem[];
    const uint32_t sbase = smem_u32(smem);
    const int tid = threadIdx.x, wid = tid >> 5, lane = tid & 31;
    const int wm = wid & 3, wn = wid >> 2;
    const int m0 = blockIdx.x * 128, n0 = blockIdx.y * 128, bz = blockIdx.z;

    const __half* srcA_h = Ah + (size_t)bz * sA + (size_t)m0 * ldA;
    const __half* srcA_l = (NPASS == 2) ? Al + (size_t)bz * sA + (size_t)m0 * ldA
                                        : nullptr;
    const __half* srcB_h = Bh + (size_t)bz * sB + (size_t)n0 * ldB;

    // copy mapping: per tile 1024 16B-segments; thread does 4: seg = j*256+tid
#define ISSUE_CHUNK(ch) do { \
        const int _k0 = (ch) * 64; \
        const uint32_t _sb = sbase + ((ch) & 1) * STAGEB; \
        _Pragma("unroll") \
        for (int j = 0; j < 4; j++) { \
            const int seg = j * 256 + tid; \
            const int r = seg >> 3, c = seg & 7; \
            const uint32_t so = (uint32_t)r * ROWB + c * 16; \
            cp16(_sb + 0*TILEB + so, srcA_h + (size_t)r*ldA + _k0 + c*8); \
            cp16(_sb + 1*TILEB + so, srcB_h + (size_t)r*ldB + _k0 + c*8); \
            if (NPASS == 2) \
                cp16(_sb + 2*TILEB + so, srcA_l + (size_t)r*ldA + _k0 + c*8); \
        } \
        CP_COMMIT(); \
    } while (0)

    float acc[2][8][4];
    #pragma unroll
    for (int i = 0; i < 2; i++)
        #pragma unroll
        for (int j = 0; j < 8; j++)
            #pragma unroll
            for (int t = 0; t < 4; t++) acc[i][j][t] = 0.0f;

    const uint32_t offA_l = (uint32_t)(lane & 15) * ROWB + (lane >> 4) * 16;
    const uint32_t offB_l = (uint32_t)((lane & 7) + ((lane & 16) ? 8 : 0)) * ROWB
                          + ((lane & 8) ? 16 : 0);

    ISSUE_CHUNK(0);

    for (int ch = 0; ch < nchunks; ch++) {
        CP_WAIT0();
        __syncthreads();
        if (ch + 1 < nchunks) ISSUE_CHUNK(ch + 1);

        const uint32_t sb = sbase + (ch & 1) * STAGEB;
        #pragma unroll
        for (int ks = 0; ks < 4; ks++) {
            const uint32_t kb = ks * 32;    // 16 halves = 32B per K-step
            uint32_t ah[2][4], al[2][4];
            #pragma unroll
            for (int i = 0; i < 2; i++) {
                uint32_t base = sb + (uint32_t)(wm * 32 + i * 16) * ROWB + kb;
                ldsm_x4(ah[i], base + 0*TILEB + offA_l);
                if (NPASS == 2) ldsm_x4(al[i], base + 2*TILEB + offA_l);
            }
            #pragma unroll
            for (int half = 0; half < 2; half++) {
                uint32_t bh[2][4];
                #pragma unroll
                for (int j2 = 0; j2 < 2; j2++) {
                    uint32_t base = sb +
                        (uint32_t)(wn * 64 + (half * 2 + j2) * 16) * ROWB + kb;
                    ldsm_x4(bh[j2], base + 1*TILEB + offB_l);
                }
                #pragma unroll
                for (int p = 0; p < NPASS; p++) {
                    #pragma unroll
                    for (int i = 0; i < 2; i++)
                        #pragma unroll
                        for (int j = 0; j < 4; j++) {
                            const uint32_t* ap = p ? al[i] : ah[i];
                            mma_fp16(acc[i][half * 4 + j], ap,
                                     &bh[j >> 1][(j & 1) * 2]);
                        }
                }
            }
        }
    }
#undef ISSUE_CHUNK

    // epilogue
    const int g = lane >> 2, tg = lane & 3;
    #pragma unroll
    for (int i = 0; i < 2; i++) {
        const int r0 = m0 + wm * 32 + i * 16 + g;
        #pragma unroll
        for (int j = 0; j < 8; j++) {
            const int c = n0 + wn * 64 + j * 8 + tg * 2;
            if (EPI == 0) {
                float* dst = Cout + (size_t)bz * sC;
                float2 v0 = make_float2(acc[i][j][0] * scale, acc[i][j][1] * scale);
                float2 v1 = make_float2(acc[i][j][2] * scale, acc[i][j][3] * scale);
                *(float2*)(dst + (size_t)r0 * ldC + c) = v0;
                *(float2*)(dst + (size_t)(r0 + 8) * ldC + c) = v1;
            } else {
                __half* oh = Oh + (size_t)bz * sC;
                float f00, f01, f10, f11;
                if (EPI == 2) {
                    float b0 = bias[r0], b1 = bias[r0 + 8];
                    f00 = elu_f(acc[i][j][0] + b0);
                    f01 = elu_f(acc[i][j][1] + b0);
                    f10 = elu_f(acc[i][j][2] + b1);
                    f11 = elu_f(acc[i][j][3] + b1);
                } else {
                    float b0 = bias[c], b1 = bias[c + 1];
                    f00 = elu_f(acc[i][j][0] + b0);
                    f01 = elu_f(acc[i][j][1] + b1);
                    f10 = elu_f(acc[i][j][2] + b0);
                    f11 = elu_f(acc[i][j][3] + b1);
                }
                __half2 h0 = __floats2half2_rn(f00, f01);
                __half2 h1 = __floats2half2_rn(f10, f11);
                *(__half2*)(oh + (size_t)r0 * ldC + c) = h0;
                *(__half2*)(oh + (size_t)(r0 + 8) * ldC + c) = h1;
                if (EPI == 1) {
                    __half* ol = Ol + (size_t)bz * sC;
                    __half2 l0 = __floats2half2_rn(f00 - __half2float(h0.x),
                                                   f01 - __half2float(h0.y));
                    __half2 l1 = __floats2half2_rn(f10 - __half2float(h1.x),
                                                   f11 - __half2float(h1.y));
                    *(__half2*)(ol + (size_t)r0 * ldC + c) = l0;
                    *(__half2*)(ol + (size_t)(r0 + 8) * ldC + c) = l1;
                }
            }
        }
    }
}

// ---------------------------------------------------------------------------
// H^T split: H[b][i][l] fp32 -> gHth/gHtl [b][l][i] fp16 hi/lo
// ---------------------------------------------------------------------------
__global__ __launch_bounds__(256) void hsplit_kernel(const float* __restrict__ H)
{
    __shared__ float t[32][33];
    const int b = blockIdx.z;
    const int l0 = blockIdx.x * 32, i0 = blockIdx.y * 32;
    const int tx = threadIdx.x & 31, ty = threadIdx.x >> 5;

    const float* Hb = H + ((size_t)b * D + i0) * L + l0;
    #pragma unroll
    for (int r = 0; r < 4; r++)
        t[ty + 8 * r][tx] = Hb[(size_t)(ty + 8 * r) * L + tx];
    __syncthreads();

    #pragma unroll
    for (int r = 0; r < 4; r++) {
        float v = t[tx][ty + 8 * r];
        size_t idx = ((size_t)b * L + l0 + ty + 8 * r) * D + i0 + tx;
        __half h = __float2half_rn(v);
        gHth[idx] = h;
        gHtl[idx] = __float2half_rn(v - __half2float(h));
    }
}

// ---------------------------------------------------------------------------
// W split: [Wk, Wq, Wv] fp32 -> gWh/gWl fp16 hi/lo
// ---------------------------------------------------------------------------
__global__ __launch_bounds__(256) void wsplit_kernel(
    const float* __restrict__ Wk, const float* __restrict__ Wq,
    const float* __restrict__ Wv)
{
    int idx = blockIdx.x * 256 + threadIdx.x;
    if (idx >= 3 * DD) return;
    int which = idx / DD, off = idx % DD;
    const float* W = (which == 0) ? Wk : (which == 1) ? Wq : Wv;
    float v = W[off];
    __half h = __float2half_rn(v);
    gWh[idx] = h;
    gWl[idx] = __float2half_rn(v - __half2float(h));
}

// ---------------------------------------------------------------------------
// Row softmax (L=2048): warp-shuffle reductions, float4 I/O, __expf.
// In place fp32 + fp16 hi output (no lo needed; C GEMM is single-pass).
// ---------------------------------------------------------------------------
__global__ __launch_bounds__(256) void softmax_kernel(float* __restrict__ A)
{
    __shared__ float red[8];
    const size_t base = (size_t)blockIdx.x * L;
    float4* rowv = (float4*)(A + base);
    const int tid = threadIdx.x, lane = tid & 31, wid = tid >> 5;

    float4 v[2];
    v[0] = rowv[tid];
    v[1] = rowv[tid + 256];

    float m = fmaxf(fmaxf(fmaxf(v[0].x, v[0].y), fmaxf(v[0].z, v[0].w)),
                    fmaxf(fmaxf(v[1].x, v[1].y), fmaxf(v[1].z, v[1].w)));
    #pragma unroll
    for (int s = 16; s > 0; s >>= 1)
        m = fmaxf(m, __shfl_xor_sync(0xFFFFFFFFu, m, s));
    if (lane == 0) red[wid] = m;
    __syncthreads();
    {
        float t = red[lane & 7];
        #pragma unroll
        for (int s = 4; s > 0; s >>= 1)
            t = fmaxf(t, __shfl_xor_sync(0xFFFFFFFFu, t, s));
        m = t;
    }

    float sum = 0.0f;
    #pragma unroll
    for (int q = 0; q < 2; q++) {
        v[q].x = __expf(v[q].x - m);
        v[q].y = __expf(v[q].y - m);
        v[q].z = __expf(v[q].z - m);
        v[q].w = __expf(v[q].w - m);
        sum += (v[q].x + v[q].y) + (v[q].z + v[q].w);
    }
    #pragma unroll
    for (int s = 16; s > 0; s >>= 1)
        sum += __shfl_xor_sync(0xFFFFFFFFu, sum, s);
    __syncthreads();
    if (lane == 0) red[wid] = sum;
    __syncthreads();
    {
        float t = red[lane & 7];
        #pragma unroll
        for (int s = 4; s > 0; s >>= 1)
            t += __shfl_xor_sync(0xFFFFFFFFu, t, s);
        sum = t;
    }
    const float inv = 1.0f / sum;

    __half2* ahp = (__half2*)(gAh + base);
    #pragma unroll
    for (int q = 0; q < 2; q++) {
        float4 a;
        a.x = v[q].x * inv; a.y = v[q].y * inv;
        a.z = v[q].z * inv; a.w = v[q].w * inv;
        rowv[tid + q * 256] = a;
        ahp[(tid + q * 256) * 2]     = __floats2half2_rn(a.x, a.y);
        ahp[(tid + q * 256) * 2 + 1] = __floats2half2_rn(a.z, a.w);
    }
}

// ---------------------------------------------------------------------------
extern "C" void kernel_launch(void* const* d_in, const int* in_sizes, int n_in,
                              void* d_out, int out_size)
{
    const float* H  = (const float*)d_in[0];
    const float* Wk = (const float*)d_in[1];
    const float* bk = (const float*)d_in[2];
    const float* Wq = (const float*)d_in[3];
    const float* bq = (const float*)d_in[4];
    const float* Wv = (const float*)d_in[5];
    const float* bv = (const float*)d_in[6];

    float* C_out = (float*)d_out;                    // [B, L, D]
    float* A_out = C_out + (size_t)B * L * D;        // [B, L, L]

    const int SM2 = SMEM_OF(2);  // 110592
    const int SM1 = SMEM_OF(1);  // 73728
    cudaFuncSetAttribute(mm2_kernel<0,2>, cudaFuncAttributeMaxDynamicSharedMemorySize, SM2);
    cudaFuncSetAttribute(mm2_kernel<1,2>, cudaFuncAttributeMaxDynamicSharedMemorySize, SM2);
    cudaFuncSetAttribute(mm2_kernel<2,2>, cudaFuncAttributeMaxDynamicSharedMemorySize, SM2);
    cudaFuncSetAttribute(mm2_kernel<3,2>, cudaFuncAttributeMaxDynamicSharedMemorySize, SM2);
    cudaFuncSetAttribute(mm2_kernel<0,1>, cudaFuncAttributeMaxDynamicSharedMemorySize, SM1);

    __half *qh, *ql, *kh, *vth, *ah, *hth, *htl, *wh, *wl;
    cudaGetSymbolAddress((void**)&qh, gQh);   cudaGetSymbolAddress((void**)&ql, gQl);
    cudaGetSymbolAddress((void**)&kh, gKh);
    cudaGetSymbolAddress((void**)&vth, gVth);
    cudaGetSymbolAddress((void**)&ah, gAh);
    cudaGetSymbolAddress((void**)&hth, gHth); cudaGetSymbolAddress((void**)&htl, gHtl);
    cudaGetSymbolAddress((void**)&wh, gWh);   cudaGetSymbolAddress((void**)&wl, gWl);

    // 0) splits
    wsplit_kernel<<<(3 * DD + 255) / 256, 256>>>(Wk, Wq, Wv);
    {
        dim3 grid(L / 32, D / 32, B);
        hsplit_kernel<<<grid, 256>>>(H);
    }

    // 1) Q = elu(Ht Wq^T + bq): split out; K: single out
    {
        dim3 grid(L / 128, D / 128, B);
        mm2_kernel<1,2><<<grid, 256, SM2>>>(
            hth, htl, (size_t)L * D, D,
            wh + 1 * DD, 0, D,
            nullptr, qh, ql, bq, (size_t)L * D, D,
            D / 64, 1.0f);
        mm2_kernel<3,2><<<grid, 256, SM2>>>(
            hth, htl, (size_t)L * D, D,
            wh + 0 * DD, 0, D,
            nullptr, kh, nullptr, bk, (size_t)L * D, D,
            D / 64, 1.0f);
    }
    // V^T = elu(Wv Ht^T + bv[row]): A=Wv(split), B=Ht(h) -> [o][l]
    {
        dim3 grid(D / 128, L / 128, B);
        mm2_kernel<2,2><<<grid, 256, SM2>>>(
            wh + 2 * DD, wl + 2 * DD, 0, D,
            hth, (size_t)L * D, D,
            nullptr, vth, nullptr, bv, (size_t)D * L, L,
            D / 64, 1.0f);
    }

    // 2) E = scale * Q K^T : A=Q(split), B=K(h)
    {
        dim3 grid(L / 128, L / 128, B);
        mm2_kernel<0,2><<<grid, 256, SM2>>>(
            qh, ql, (size_t)L * D, D,
            kh, (size_t)L * D, D,
            A_out, nullptr, nullptr, nullptr, (size_t)L * L, L,
            D / 64, 0.044194173824159216f);
    }

    // 3) softmax rows + fp16 A (hi only)
    softmax_kernel<<<B * L, 256>>>(A_out);

    // 4) C = A V : A=A(hi, single pass), B=V^T(h)
    {
        dim3 grid(L / 128, D / 128, B);
        mm2_kernel<0,1><<<grid, 256, SM1>>>(
            ah, nullptr, (size_t)L * L, L,
            vth, (size_t)D * L, L,
            C_out, nullptr, nullptr, nullptr, (size_t)L * D, D,
            L / 64, 1.0f);
    }
}

// round 9
// speedup vs baseline: 5.2507x; 1.3472x over previous
#include <cuda_runtime.h>
#include <cuda_fp16.h>
#include <math.h>
#include <stdint.h>

#define B 8
#define D 512
#define L 2048
#define DD (512*512)

#define BLD (8u*2048u*512u)            // 8388608
#define BLL (8ull*2048ull*2048ull)     // 33554432

// single-fp16 operands
__device__ __align__(128) __half gQ[BLD];
__device__ __align__(128) __half gK[BLD];
__device__ __align__(128) __half gVt[BLD];                 // V^T: [b][d][l]
__device__ __align__(128) __half gA[BLL];                  // softmax fp16
__device__ __align__(128) __half gHt[BLD];                 // H^T: [b][l][i]
__device__ __align__(128) __half gW[3*DD];                 // [Wk,Wq,Wv][o][i]

// ---------------------------------------------------------------------------
__device__ __forceinline__ uint32_t smem_u32(const void* p) {
    uint32_t a;
    asm("{ .reg .u64 t; cvta.to.shared.u64 t, %1; cvt.u32.u64 %0, t; }"
        : "=r"(a) : "l"(p));
    return a;
}

__device__ __forceinline__ void ldsm_x4(uint32_t* r, uint32_t addr) {
    asm volatile("ldmatrix.sync.aligned.m8n8.x4.shared.b16 {%0,%1,%2,%3}, [%4];"
        : "=r"(r[0]), "=r"(r[1]), "=r"(r[2]), "=r"(r[3]) : "r"(addr));
}

__device__ __forceinline__ void mma_fp16(float* c, const uint32_t* a, const uint32_t* b) {
    asm volatile(
        "mma.sync.aligned.m16n8k16.row.col.f32.f16.f16.f32 "
        "{%0,%1,%2,%3}, {%4,%5,%6,%7}, {%8,%9}, {%0,%1,%2,%3};"
        : "+f"(c[0]), "+f"(c[1]), "+f"(c[2]), "+f"(c[3])
        : "r"(a[0]), "r"(a[1]), "r"(a[2]), "r"(a[3]), "r"(b[0]), "r"(b[1]));
}

__device__ __forceinline__ void cp16(uint32_t saddr, const void* gaddr) {
    asm volatile("cp.async.cg.shared.global [%0], [%1], 16;"
        :: "r"(saddr), "l"(gaddr) : "memory");
}
#define CP_COMMIT() asm volatile("cp.async.commit_group;" ::: "memory")
#define CP_WAIT0()  asm volatile("cp.async.wait_group 0;" ::: "memory")

__device__ __forceinline__ float elu_f(float x) {
    return x > 0.0f ? x : expm1f(x);
}

// ---------------------------------------------------------------------------
// Single-pass fp16 GEMM: acc[m,n] = sum_k A[m,k] * Bm[n,k]
// CTA tile 128x128, K-chunk 64. 8 warps = (wm 0..3)x(wn 0..1), 32x64 each.
// 2 CTAs/SM; single __syncthreads per chunk; 2 smem tiles per stage.
// EPI 0: Cout = scale*acc (fp32)
// EPI 2: fp16 of elu(acc + bias[row])
// EPI 3: fp16 of elu(acc + bias[col])
// ---------------------------------------------------------------------------
#define ROWB  144                    // 64 halves (128B) + 16B pad
#define TILEB (128 * ROWB)           // 18432
#define STAGEB (2 * TILEB)           // 36864
#define MM_SMEM (2 * STAGEB)         // 73728

template<int EPI>
__global__ __launch_bounds__(256, 2) void mm_kernel(
    const __half* __restrict__ Am, size_t sA, int ldA,
    const __half* __restrict__ Bm, size_t sB, int ldB,
    float* __restrict__ Cout, __half* __restrict__ Oh,
    const float* __restrict__ bias,
    size_t sC, int ldC,
    int nchunks, float scale)
{
    extern __shared__ char smem[];
    const uint32_t sbase = smem_u32(smem);
    const int tid = threadIdx.x, wid = tid >> 5, lane = tid & 31;
    const int wm = wid & 3, wn = wid >> 2;
    const int m0 = blockIdx.x * 128, n0 = blockIdx.y * 128, bz = blockIdx.z;

    const __half* srcA = Am + (size_t)bz * sA + (size_t)m0 * ldA;
    const __half* srcB = Bm + (size_t)bz * sB + (size_t)n0 * ldB;

    // copy: per tile 1024 16B-segments; each thread does 4: seg = j*256+tid
#define ISSUE_CHUNK(ch) do { \
        const int _k0 = (ch) * 64; \
        const uint32_t _sb = sbase + ((ch) & 1) * STAGEB; \
        _Pragma("unroll") \
        for (int j = 0; j < 4; j++) { \
            const int seg = j * 256 + tid; \
            const int r = seg >> 3, c = seg & 7; \
            const uint32_t so = (uint32_t)r * ROWB + c * 16; \
            cp16(_sb + 0*TILEB + so, srcA + (size_t)r*ldA + _k0 + c*8); \
            cp16(_sb + 1*TILEB + so, srcB + (size_t)r*ldB + _k0 + c*8); \
        } \
        CP_COMMIT(); \
    } while (0)

    float acc[2][8][4];
    #pragma unroll
    for (int i = 0; i < 2; i++)
        #pragma unroll
        for (int j = 0; j < 8; j++)
            #pragma unroll
            for (int t = 0; t < 4; t++) acc[i][j][t] = 0.0f;

    const uint32_t offA_l = (uint32_t)(lane & 15) * ROWB + (lane >> 4) * 16;
    const uint32_t offB_l = (uint32_t)((lane & 7) + ((lane & 16) ? 8 : 0)) * ROWB
                          + ((lane & 8) ? 16 : 0);

    ISSUE_CHUNK(0);

    for (int ch = 0; ch < nchunks; ch++) {
        CP_WAIT0();
        __syncthreads();
        if (ch + 1 < nchunks) ISSUE_CHUNK(ch + 1);

        const uint32_t sb = sbase + (ch & 1) * STAGEB;
        #pragma unroll
        for (int ks = 0; ks < 4; ks++) {
            const uint32_t kb = ks * 32;    // 16 halves = 32B per K-step
            uint32_t ah[2][4];
            #pragma unroll
            for (int i = 0; i < 2; i++) {
                uint32_t base = sb + (uint32_t)(wm * 32 + i * 16) * ROWB + kb;
                ldsm_x4(ah[i], base + 0*TILEB + offA_l);
            }
            #pragma unroll
            for (int half = 0; half < 2; half++) {
                uint32_t bh[2][4];
                #pragma unroll
                for (int j2 = 0; j2 < 2; j2++) {
                    uint32_t base = sb +
                        (uint32_t)(wn * 64 + (half * 2 + j2) * 16) * ROWB + kb;
                    ldsm_x4(bh[j2], base + 1*TILEB + offB_l);
                }
                #pragma unroll
                for (int i = 0; i < 2; i++)
                    #pragma unroll
                    for (int j = 0; j < 4; j++)
                        mma_fp16(acc[i][half * 4 + j], ah[i],
                                 &bh[j >> 1][(j & 1) * 2]);
            }
        }
    }
#undef ISSUE_CHUNK

    // epilogue
    const int g = lane >> 2, tg = lane & 3;
    #pragma unroll
    for (int i = 0; i < 2; i++) {
        const int r0 = m0 + wm * 32 + i * 16 + g;
        #pragma unroll
        for (int j = 0; j < 8; j++) {
            const int c = n0 + wn * 64 + j * 8 + tg * 2;
            if (EPI == 0) {
                float* dst = Cout + (size_t)bz * sC;
                float2 v0 = make_float2(acc[i][j][0] * scale, acc[i][j][1] * scale);
                float2 v1 = make_float2(acc[i][j][2] * scale, acc[i][j][3] * scale);
                *(float2*)(dst + (size_t)r0 * ldC + c) = v0;
                *(float2*)(dst + (size_t)(r0 + 8) * ldC + c) = v1;
            } else {
                __half* oh = Oh + (size_t)bz * sC;
                float f00, f01, f10, f11;
                if (EPI == 2) {
                    float b0 = bias[r0], b1 = bias[r0 + 8];
                    f00 = elu_f(acc[i][j][0] + b0);
                    f01 = elu_f(acc[i][j][1] + b0);
                    f10 = elu_f(acc[i][j][2] + b1);
                    f11 = elu_f(acc[i][j][3] + b1);
                } else {
                    float b0 = bias[c], b1 = bias[c + 1];
                    f00 = elu_f(acc[i][j][0] + b0);
                    f01 = elu_f(acc[i][j][1] + b1);
                    f10 = elu_f(acc[i][j][2] + b0);
                    f11 = elu_f(acc[i][j][3] + b1);
                }
                *(__half2*)(oh + (size_t)r0 * ldC + c) = __floats2half2_rn(f00, f01);
                *(__half2*)(oh + (size_t)(r0 + 8) * ldC + c) = __floats2half2_rn(f10, f11);
            }
        }
    }
}

// ---------------------------------------------------------------------------
// H^T: H[b][i][l] fp32 -> gHt [b][l][i] fp16
// ---------------------------------------------------------------------------
__global__ __launch_bounds__(256) void hsplit_kernel(const float* __restrict__ H)
{
    __shared__ float t[32][33];
    const int b = blockIdx.z;
    const int l0 = blockIdx.x * 32, i0 = blockIdx.y * 32;
    const int tx = threadIdx.x & 31, ty = threadIdx.x >> 5;

    const float* Hb = H + ((size_t)b * D + i0) * L + l0;
    #pragma unroll
    for (int r = 0; r < 4; r++)
        t[ty + 8 * r][tx] = Hb[(size_t)(ty + 8 * r) * L + tx];
    __syncthreads();

    #pragma unroll
    for (int r = 0; r < 4; r++) {
        float v = t[tx][ty + 8 * r];
        size_t idx = ((size_t)b * L + l0 + ty + 8 * r) * D + i0 + tx;
        gHt[idx] = __float2half_rn(v);
    }
}

// ---------------------------------------------------------------------------
// W convert: [Wk, Wq, Wv] fp32 -> gW fp16
// ---------------------------------------------------------------------------
__global__ __launch_bounds__(256) void wsplit_kernel(
    const float* __restrict__ Wk, const float* __restrict__ Wq,
    const float* __restrict__ Wv)
{
    int idx = blockIdx.x * 256 + threadIdx.x;
    if (idx >= 3 * DD) return;
    int which = idx / DD, off = idx % DD;
    const float* W = (which == 0) ? Wk : (which == 1) ? Wq : Wv;
    gW[idx] = __float2half_rn(W[off]);
}

// ---------------------------------------------------------------------------
// Row softmax (L=2048): warp-shuffle reductions, float4 I/O, __expf.
// In place fp32 + fp16 output.
// ---------------------------------------------------------------------------
__global__ __launch_bounds__(256) void softmax_kernel(float* __restrict__ A)
{
    __shared__ float red[8];
    const size_t base = (size_t)blockIdx.x * L;
    float4* rowv = (float4*)(A + base);
    const int tid = threadIdx.x, lane = tid & 31, wid = tid >> 5;

    float4 v[2];
    v[0] = rowv[tid];
    v[1] = rowv[tid + 256];

    float m = fmaxf(fmaxf(fmaxf(v[0].x, v[0].y), fmaxf(v[0].z, v[0].w)),
                    fmaxf(fmaxf(v[1].x, v[1].y), fmaxf(v[1].z, v[1].w)));
    #pragma unroll
    for (int s = 16; s > 0; s >>= 1)
        m = fmaxf(m, __shfl_xor_sync(0xFFFFFFFFu, m, s));
    if (lane == 0) red[wid] = m;
    __syncthreads();
    {
        float t = red[lane & 7];
        #pragma unroll
        for (int s = 4; s > 0; s >>= 1)
            t = fmaxf(t, __shfl_xor_sync(0xFFFFFFFFu, t, s));
        m = t;
    }

    float sum = 0.0f;
    #pragma unroll
    for (int q = 0; q < 2; q++) {
        v[q].x = __expf(v[q].x - m);
        v[q].y = __expf(v[q].y - m);
        v[q].z = __expf(v[q].z - m);
        v[q].w = __expf(v[q].w - m);
        sum += (v[q].x + v[q].y) + (v[q].z + v[q].w);
    }
    #pragma unroll
    for (int s = 16; s > 0; s >>= 1)
        sum += __shfl_xor_sync(0xFFFFFFFFu, sum, s);
    __syncthreads();
    if (lane == 0) red[wid] = sum;
    __syncthreads();
    {
        float t = red[lane & 7];
        #pragma unroll
        for (int s = 4; s > 0; s >>= 1)
            t += __shfl_xor_sync(0xFFFFFFFFu, t, s);
        sum = t;
    }
    const float inv = 1.0f / sum;

    __half2* ap = (__half2*)(gA + base);
    #pragma unroll
    for (int q = 0; q < 2; q++) {
        float4 a;
        a.x = v[q].x * inv; a.y = v[q].y * inv;
        a.z = v[q].z * inv; a.w = v[q].w * inv;
        rowv[tid + q * 256] = a;
        ap[(tid + q * 256) * 2]     = __floats2half2_rn(a.x, a.y);
        ap[(tid + q * 256) * 2 + 1] = __floats2half2_rn(a.z, a.w);
    }
}

// ---------------------------------------------------------------------------
extern "C" void kernel_launch(void* const* d_in, const int* in_sizes, int n_in,
                              void* d_out, int out_size)
{
    const float* H  = (const float*)d_in[0];
    const float* Wk = (const float*)d_in[1];
    const float* bk = (const float*)d_in[2];
    const float* Wq = (const float*)d_in[3];
    const float* bq = (const float*)d_in[4];
    const float* Wv = (const float*)d_in[5];
    const float* bv = (const float*)d_in[6];

    float* C_out = (float*)d_out;                    // [B, L, D]
    float* A_out = C_out + (size_t)B * L * D;        // [B, L, L]

    cudaFuncSetAttribute(mm_kernel<0>, cudaFuncAttributeMaxDynamicSharedMemorySize, MM_SMEM);
    cudaFuncSetAttribute(mm_kernel<2>, cudaFuncAttributeMaxDynamicSharedMemorySize, MM_SMEM);
    cudaFuncSetAttribute(mm_kernel<3>, cudaFuncAttributeMaxDynamicSharedMemorySize, MM_SMEM);

    __half *q, *k, *vt, *a, *ht, *w;
    cudaGetSymbolAddress((void**)&q, gQ);
    cudaGetSymbolAddress((void**)&k, gK);
    cudaGetSymbolAddress((void**)&vt, gVt);
    cudaGetSymbolAddress((void**)&a, gA);
    cudaGetSymbolAddress((void**)&ht, gHt);
    cudaGetSymbolAddress((void**)&w, gW);

    // 0) converts
    wsplit_kernel<<<(3 * DD + 255) / 256, 256>>>(Wk, Wq, Wv);
    {
        dim3 grid(L / 32, D / 32, B);
        hsplit_kernel<<<grid, 256>>>(H);
    }

    // 1) Q = elu(Ht Wq^T + bq), K = elu(Ht Wk^T + bk)   -> [l][o] fp16
    {
        dim3 grid(L / 128, D / 128, B);
        mm_kernel<3><<<grid, 256, MM_SMEM>>>(
            ht, (size_t)L * D, D,
            w + 1 * DD, 0, D,
            nullptr, q, bq, (size_t)L * D, D,
            D / 64, 1.0f);
        mm_kernel<3><<<grid, 256, MM_SMEM>>>(
            ht, (size_t)L * D, D,
            w + 0 * DD, 0, D,
            nullptr, k, bk, (size_t)L * D, D,
            D / 64, 1.0f);
    }
    // V^T = elu(Wv Ht^T + bv[row]) -> [o][l] fp16
    {
        dim3 grid(D / 128, L / 128, B);
        mm_kernel<2><<<grid, 256, MM_SMEM>>>(
            w + 2 * DD, 0, D,
            ht, (size_t)L * D, D,
            nullptr, vt, bv, (size_t)D * L, L,
            D / 64, 1.0f);
    }

    // 2) E = scale * Q K^T
    {
        dim3 grid(L / 128, L / 128, B);
        mm_kernel<0><<<grid, 256, MM_SMEM>>>(
            q, (size_t)L * D, D,
            k, (size_t)L * D, D,
            A_out, nullptr, nullptr, (size_t)L * L, L,
            D / 64, 0.044194173824159216f);
    }

    // 3) softmax rows + fp16 A
    softmax_kernel<<<B * L, 256>>>(A_out);

    // 4) C = A V
    {
        dim3 grid(L / 128, D / 128, B);
        mm_kernel<0><<<grid, 256, MM_SMEM>>>(
            a, (size_t)L * L, L,
            vt, (size_t)D * L, L,
            C_out, nullptr, nullptr, (size_t)L * D, D,
            L / 64, 1.0f);
    }
}

// round 10
// speedup vs baseline: 5.9524x; 1.1336x over previous
#include <cuda_runtime.h>
#include <cuda_fp16.h>
#include <math.h>
#include <stdint.h>

#define B 8
#define D 512
#define L 2048
#define DD (512*512)

#define BLD (8u*2048u*512u)            // 8388608
#define BLL (8ull*2048ull*2048ull)     // 33554432

// single-fp16 operands
__device__ __align__(128) __half gQ[BLD];
__device__ __align__(128) __half gK[BLD];
__device__ __align__(128) __half gVt[BLD];                 // V^T: [b][d][l]
__device__ __align__(128) __half gA[BLL];                  // softmax fp16
__device__ __align__(128) __half gHt[BLD];                 // H^T: [b][l][i]
__device__ __align__(128) __half gW[3*DD];                 // [Wk,Wq,Wv][o][i]

// ---------------------------------------------------------------------------
__device__ __forceinline__ uint32_t smem_u32(const void* p) {
    uint32_t a;
    asm("{ .reg .u64 t; cvta.to.shared.u64 t, %1; cvt.u32.u64 %0, t; }"
        : "=r"(a) : "l"(p));
    return a;
}

__device__ __forceinline__ void ldsm_x4(uint32_t* r, uint32_t addr) {
    asm volatile("ldmatrix.sync.aligned.m8n8.x4.shared.b16 {%0,%1,%2,%3}, [%4];"
        : "=r"(r[0]), "=r"(r[1]), "=r"(r[2]), "=r"(r[3]) : "r"(addr));
}

__device__ __forceinline__ void mma_fp16(float* c, const uint32_t* a, const uint32_t* b) {
    asm volatile(
        "mma.sync.aligned.m16n8k16.row.col.f32.f16.f16.f32 "
        "{%0,%1,%2,%3}, {%4,%5,%6,%7}, {%8,%9}, {%0,%1,%2,%3};"
        : "+f"(c[0]), "+f"(c[1]), "+f"(c[2]), "+f"(c[3])
        : "r"(a[0]), "r"(a[1]), "r"(a[2]), "r"(a[3]), "r"(b[0]), "r"(b[1]));
}

__device__ __forceinline__ void cp16(uint32_t saddr, const void* gaddr) {
    asm volatile("cp.async.cg.shared.global [%0], [%1], 16;"
        :: "r"(saddr), "l"(gaddr) : "memory");
}
#define CP_COMMIT() asm volatile("cp.async.commit_group;" ::: "memory")
#define CP_WAIT1()  asm volatile("cp.async.wait_group 1;" ::: "memory")
#define CP_WAIT0()  asm volatile("cp.async.wait_group 0;" ::: "memory")

__device__ __forceinline__ float elu_f(float x) {
    return x > 0.0f ? x : expm1f(x);
}

// ---------------------------------------------------------------------------
// Single-pass fp16 GEMM: acc[m,n] = sum_k A[m,k] * Bm[n,k]
// CTA tile 128x128, K-chunk 64, NCH chunks (compile-time). 8 warps, 32x64 each.
// 2 CTAs/SM; 3-stage cp.async pipeline; one __syncthreads per chunk.
// MERGED: grid.z = 2*B, z&1 selects {B-matrix, bias, output} pair (Q/K proj).
// EPI 0: Cout = scale*acc (fp32)
// EPI 2: fp16 of elu(acc + bias[row])
// EPI 3: fp16 of elu(acc + bias[col])
// ---------------------------------------------------------------------------
#define ROWB  144                    // 64 halves (128B) + 16B pad
#define TILEB (128 * ROWB)           // 18432
#define STAGEB (2 * TILEB)           // 36864
#define MM_SMEM (3 * STAGEB)         // 110592

template<int EPI, int NCH, int MERGED>
__global__ __launch_bounds__(256, 2) void mm_kernel(
    const __half* __restrict__ Am, size_t sA, int ldA,
    const __half* __restrict__ Bm, size_t sB, int ldB,
    float* __restrict__ Cout,
    __half* __restrict__ O0, __half* __restrict__ O1,
    const float* __restrict__ bias0, const float* __restrict__ bias1,
    size_t sC, int ldC, float scale)
{
    extern __shared__ char smem[];
    const uint32_t sbase = smem_u32(smem);
    const int tid = threadIdx.x, wid = tid >> 5, lane = tid & 31;
    const int wm = wid & 3, wn = wid >> 2;
    const int m0 = blockIdx.x * 128, n0 = blockIdx.y * 128;
    const int bz = MERGED ? (int)(blockIdx.z >> 1) : (int)blockIdx.z;
    const int which = MERGED ? (int)(blockIdx.z & 1) : 0;

    const __half* srcA = Am + (size_t)bz * sA + (size_t)m0 * ldA;
    const __half* srcB = Bm + (size_t)(MERGED ? which : bz) * sB
                            + (size_t)n0 * ldB;

    // copy: per tile 1024 16B-segments; each thread does 4: seg = j*256+tid
#define ISSUE_CHUNK(ch, stg) do { \
        const int _k0 = (ch) * 64; \
        const uint32_t _sb = sbase + (stg) * STAGEB; \
        _Pragma("unroll") \
        for (int j = 0; j < 4; j++) { \
            const int seg = j * 256 + tid; \
            const int r = seg >> 3, c = seg & 7; \
            const uint32_t so = (uint32_t)r * ROWB + c * 16; \
            cp16(_sb + 0*TILEB + so, srcA + (size_t)r*ldA + _k0 + c*8); \
            cp16(_sb + 1*TILEB + so, srcB + (size_t)r*ldB + _k0 + c*8); \
        } \
        CP_COMMIT(); \
    } while (0)

    float acc[2][8][4];
    #pragma unroll
    for (int i = 0; i < 2; i++)
        #pragma unroll
        for (int j = 0; j < 8; j++)
            #pragma unroll
            for (int t = 0; t < 4; t++) acc[i][j][t] = 0.0f;

    const uint32_t offA_l = (uint32_t)(lane & 15) * ROWB + (lane >> 4) * 16;
    const uint32_t offB_l = (uint32_t)((lane & 7) + ((lane & 16) ? 8 : 0)) * ROWB
                          + ((lane & 8) ? 16 : 0);

    ISSUE_CHUNK(0, 0);
    if (NCH > 1) ISSUE_CHUNK(1, 1);

    int sstage = 0;
    #pragma unroll
    for (int ch = 0; ch < NCH; ch++) {
        if (ch + 1 < NCH) { CP_WAIT1(); } else { CP_WAIT0(); }
        __syncthreads();
        if (ch + 2 < NCH) {
            int nstage = sstage + 2; if (nstage >= 3) nstage -= 3;
            ISSUE_CHUNK(ch + 2, nstage);
        }

        const uint32_t sb = sbase + sstage * STAGEB;
        #pragma unroll
        for (int ks = 0; ks < 4; ks++) {
            const uint32_t kb = ks * 32;    // 16 halves = 32B per K-step
            uint32_t ah[2][4];
            #pragma unroll
            for (int i = 0; i < 2; i++) {
                uint32_t base = sb + (uint32_t)(wm * 32 + i * 16) * ROWB + kb;
                ldsm_x4(ah[i], base + 0*TILEB + offA_l);
            }
            #pragma unroll
            for (int half = 0; half < 2; half++) {
                uint32_t bh[2][4];
                #pragma unroll
                for (int j2 = 0; j2 < 2; j2++) {
                    uint32_t base = sb +
                        (uint32_t)(wn * 64 + (half * 2 + j2) * 16) * ROWB + kb;
                    ldsm_x4(bh[j2], base + 1*TILEB + offB_l);
                }
                #pragma unroll
                for (int i = 0; i < 2; i++)
                    #pragma unroll
                    for (int j = 0; j < 4; j++)
                        mma_fp16(acc[i][half * 4 + j], ah[i],
                                 &bh[j >> 1][(j & 1) * 2]);
            }
        }
        sstage = (sstage + 1 == 3) ? 0 : sstage + 1;
    }
#undef ISSUE_CHUNK

    // epilogue
    const int g = lane >> 2, tg = lane & 3;
    const float* bias = (MERGED && which) ? bias1 : bias0;
    __half* Oh = (MERGED && which) ? O1 : O0;
    #pragma unroll
    for (int i = 0; i < 2; i++) {
        const int r0 = m0 + wm * 32 + i * 16 + g;
        #pragma unroll
        for (int j = 0; j < 8; j++) {
            const int c = n0 + wn * 64 + j * 8 + tg * 2;
            if (EPI == 0) {
                float* dst = Cout + (size_t)bz * sC;
                float2 v0 = make_float2(acc[i][j][0] * scale, acc[i][j][1] * scale);
                float2 v1 = make_float2(acc[i][j][2] * scale, acc[i][j][3] * scale);
                *(float2*)(dst + (size_t)r0 * ldC + c) = v0;
                *(float2*)(dst + (size_t)(r0 + 8) * ldC + c) = v1;
            } else {
                __half* oh = Oh + (size_t)bz * sC;
                float f00, f01, f10, f11;
                if (EPI == 2) {
                    float b0 = bias[r0], b1 = bias[r0 + 8];
                    f00 = elu_f(acc[i][j][0] + b0);
                    f01 = elu_f(acc[i][j][1] + b0);
                    f10 = elu_f(acc[i][j][2] + b1);
                    f11 = elu_f(acc[i][j][3] + b1);
                } else {
                    float b0 = bias[c], b1 = bias[c + 1];
                    f00 = elu_f(acc[i][j][0] + b0);
                    f01 = elu_f(acc[i][j][1] + b1);
                    f10 = elu_f(acc[i][j][2] + b0);
                    f11 = elu_f(acc[i][j][3] + b1);
                }
                *(__half2*)(oh + (size_t)r0 * ldC + c) = __floats2half2_rn(f00, f01);
                *(__half2*)(oh + (size_t)(r0 + 8) * ldC + c) = __floats2half2_rn(f10, f11);
            }
        }
    }
}

// ---------------------------------------------------------------------------
// H^T: H[b][i][l] fp32 -> gHt [b][l][i] fp16
// ---------------------------------------------------------------------------
__global__ __launch_bounds__(256) void hsplit_kernel(const float* __restrict__ H)
{
    __shared__ float t[32][33];
    const int b = blockIdx.z;
    const int l0 = blockIdx.x * 32, i0 = blockIdx.y * 32;
    const int tx = threadIdx.x & 31, ty = threadIdx.x >> 5;

    const float* Hb = H + ((size_t)b * D + i0) * L + l0;
    #pragma unroll
    for (int r = 0; r < 4; r++)
        t[ty + 8 * r][tx] = Hb[(size_t)(ty + 8 * r) * L + tx];
    __syncthreads();

    #pragma unroll
    for (int r = 0; r < 4; r++) {
        float v = t[tx][ty + 8 * r];
        size_t idx = ((size_t)b * L + l0 + ty + 8 * r) * D + i0 + tx;
        gHt[idx] = __float2half_rn(v);
    }
}

// ---------------------------------------------------------------------------
// W convert: [Wk, Wq, Wv] fp32 -> gW fp16
// ---------------------------------------------------------------------------
__global__ __launch_bounds__(256) void wsplit_kernel(
    const float* __restrict__ Wk, const float* __restrict__ Wq,
    const float* __restrict__ Wv)
{
    int idx = blockIdx.x * 256 + threadIdx.x;
    if (idx >= 3 * DD) return;
    int which = idx / DD, off = idx % DD;
    const float* W = (which == 0) ? Wk : (which == 1) ? Wq : Wv;
    gW[idx] = __float2half_rn(W[off]);
}

// ---------------------------------------------------------------------------
// Row softmax (L=2048): warp-shuffle reductions, float4 I/O, __expf.
// In place fp32 + fp16 output.
// ---------------------------------------------------------------------------
__global__ __launch_bounds__(256) void softmax_kernel(float* __restrict__ A)
{
    __shared__ float red[8];
    const size_t base = (size_t)blockIdx.x * L;
    float4* rowv = (float4*)(A + base);
    const int tid = threadIdx.x, lane = tid & 31, wid = tid >> 5;

    float4 v[2];
    v[0] = rowv[tid];
    v[1] = rowv[tid + 256];

    float m = fmaxf(fmaxf(fmaxf(v[0].x, v[0].y), fmaxf(v[0].z, v[0].w)),
                    fmaxf(fmaxf(v[1].x, v[1].y), fmaxf(v[1].z, v[1].w)));
    #pragma unroll
    for (int s = 16; s > 0; s >>= 1)
        m = fmaxf(m, __shfl_xor_sync(0xFFFFFFFFu, m, s));
    if (lane == 0) red[wid] = m;
    __syncthreads();
    {
        float t = red[lane & 7];
        #pragma unroll
        for (int s = 4; s > 0; s >>= 1)
            t = fmaxf(t, __shfl_xor_sync(0xFFFFFFFFu, t, s));
        m = t;
    }

    float sum = 0.0f;
    #pragma unroll
    for (int q = 0; q < 2; q++) {
        v[q].x = __expf(v[q].x - m);
        v[q].y = __expf(v[q].y - m);
        v[q].z = __expf(v[q].z - m);
        v[q].w = __expf(v[q].w - m);
        sum += (v[q].x + v[q].y) + (v[q].z + v[q].w);
    }
    #pragma unroll
    for (int s = 16; s > 0; s >>= 1)
        sum += __shfl_xor_sync(0xFFFFFFFFu, sum, s);
    __syncthreads();
    if (lane == 0) red[wid] = sum;
    __syncthreads();
    {
        float t = red[lane & 7];
        #pragma unroll
        for (int s = 4; s > 0; s >>= 1)
            t += __shfl_xor_sync(0xFFFFFFFFu, t, s);
        sum = t;
    }
    const float inv = 1.0f / sum;

    __half2* ap = (__half2*)(gA + base);
    #pragma unroll
    for (int q = 0; q < 2; q++) {
        float4 a;
        a.x = v[q].x * inv; a.y = v[q].y * inv;
        a.z = v[q].z * inv; a.w = v[q].w * inv;
        rowv[tid + q * 256] = a;
        ap[(tid + q * 256) * 2]     = __floats2half2_rn(a.x, a.y);
        ap[(tid + q * 256) * 2 + 1] = __floats2half2_rn(a.z, a.w);
    }
}

// ---------------------------------------------------------------------------
extern "C" void kernel_launch(void* const* d_in, const int* in_sizes, int n_in,
                              void* d_out, int out_size)
{
    const float* H  = (const float*)d_in[0];
    const float* Wk = (const float*)d_in[1];
    const float* bk = (const float*)d_in[2];
    const float* Wq = (const float*)d_in[3];
    const float* bq = (const float*)d_in[4];
    const float* Wv = (const float*)d_in[5];
    const float* bv = (const float*)d_in[6];

    float* C_out = (float*)d_out;                    // [B, L, D]
    float* A_out = C_out + (size_t)B * L * D;        // [B, L, L]

    cudaFuncSetAttribute(mm_kernel<0,8,0>,  cudaFuncAttributeMaxDynamicSharedMemorySize, MM_SMEM);
    cudaFuncSetAttribute(mm_kernel<0,32,0>, cudaFuncAttributeMaxDynamicSharedMemorySize, MM_SMEM);
    cudaFuncSetAttribute(mm_kernel<2,8,0>,  cudaFuncAttributeMaxDynamicSharedMemorySize, MM_SMEM);
    cudaFuncSetAttribute(mm_kernel<3,8,1>,  cudaFuncAttributeMaxDynamicSharedMemorySize, MM_SMEM);

    __half *q, *k, *vt, *a, *ht, *w;
    cudaGetSymbolAddress((void**)&q, gQ);
    cudaGetSymbolAddress((void**)&k, gK);
    cudaGetSymbolAddress((void**)&vt, gVt);
    cudaGetSymbolAddress((void**)&a, gA);
    cudaGetSymbolAddress((void**)&ht, gHt);
    cudaGetSymbolAddress((void**)&w, gW);

    // 0) converts
    wsplit_kernel<<<(3 * DD + 255) / 256, 256>>>(Wk, Wq, Wv);
    {
        dim3 grid(L / 32, D / 32, B);
        hsplit_kernel<<<grid, 256>>>(H);
    }

    // 1) merged K(z even) / Q(z odd) projection: elu(Ht W^T + b) -> [l][o] fp16
    {
        dim3 grid(L / 128, D / 128, 2 * B);
        mm_kernel<3,8,1><<<grid, 256, MM_SMEM>>>(
            ht, (size_t)L * D, D,
            w, (size_t)DD, D,            // which-stride = DD (Wk then Wq)
            nullptr, k, q, bk, bq,
            (size_t)L * D, D, 1.0f);
    }
    // V^T = elu(Wv Ht^T + bv[row]) -> [o][l] fp16
    {
        dim3 grid(D / 128, L / 128, B);
        mm_kernel<2,8,0><<<grid, 256, MM_SMEM>>>(
            w + 2 * DD, 0, D,
            ht, (size_t)L * D, D,
            nullptr, vt, nullptr, bv, nullptr,
            (size_t)D * L, L, 1.0f);
    }

    // 2) E = scale * Q K^T
    {
        dim3 grid(L / 128, L / 128, B);
        mm_kernel<0,8,0><<<grid, 256, MM_SMEM>>>(
            q, (size_t)L * D, D,
            k, (size_t)L * D, D,
            A_out, nullptr, nullptr, nullptr, nullptr,
            (size_t)L * L, L, 0.044194173824159216f);
    }

    // 3) softmax rows + fp16 A
    softmax_kernel<<<B * L, 256>>>(A_out);

    // 4) C = A V
    {
        dim3 grid(L / 128, D / 128, B);
        mm_kernel<0,32,0><<<grid, 256, MM_SMEM>>>(
            a, (size_t)L * L, L,
            vt, (size_t)D * L, L,
            C_out, nullptr, nullptr, nullptr, nullptr,
            (size_t)L * D, D, 1.0f);
    }
}